// round 10
// baseline (speedup 1.0000x reference)
#include <cuda_runtime.h>
#include <cstdint>

#define DIM   384
#define MAXM  16
#define MAXN  50000
#define NB    4096                 // buckets per row (top 12 bits of sortable key)
#define BSHIFT 20                  // 32 - 12
#define FXS   1099511627776.0      // 2^40 fixed-point scale

// ---- sim kernel geometry ----
#define TILE_DOCS 48
#define ROWP      388              // padded corpus row stride in floats
#define SIM_TPB   256
#define SIM_BLOCKS 148
#define BFRAG_U4  (2 * 12 * 32)                   // 768 uint4 per table
#define OFF_TA    0
#define OFF_TB    (BFRAG_U4 * 4)                  // 3072 floats
#define OFF_TILES (2 * BFRAG_U4 * 4)              // 6144
#define TILE_F    (TILE_DOCS * ROWP)              // 18624
#define OFF_PART  (OFF_TILES + 2 * TILE_F)        // 43392
#define PART_F    (2 * TILE_DOCS * 17)            // 1632
#define OFF_INV   (OFF_PART + PART_F)             // 45024
#define OFF_MBAR  (OFF_INV + TILE_DOCS)           // 45072 (8B-aligned in bytes)
#define SMEM_FLOATS (OFF_MBAR + 8)
#define SMEM_DYN  (SMEM_FLOATS * (int)sizeof(float))   // ~180 KB

#define PAVB_TPB 256
#define BPT (NB / PAVB_TPB)              // 16 buckets per thread
#define PAVB_SMEM (NB * (int)(sizeof(double) + 2 * sizeof(int)))   // 64 KB

// ---- static device scratch (no allocations allowed) ----
__device__ float              g_qn[MAXM * DIM];
__device__ int                g_cnt[MAXM * NB];
__device__ unsigned long long g_sum[MAXM * NB];
__device__ float              g_dualf[MAXM * NB];

__device__ __forceinline__ unsigned sortable(float f) {
    unsigned u = __float_as_uint(f);
    return (u & 0x80000000u) ? ~u : (u | 0x80000000u);   // ascending order
}

// pack two f32 -> bf16x2 (lo half = first arg, hi half = second arg)
__device__ __forceinline__ unsigned packbf(float lo, float hi) {
    unsigned r;
    asm("cvt.rn.bf16x2.f32 %0, %1, %2;" : "=r"(r) : "f"(hi), "f"(lo));
    return r;
}
__device__ __forceinline__ float bflo(unsigned u) { return __uint_as_float(u << 16); }
__device__ __forceinline__ float bfhi(unsigned u) { return __uint_as_float(u & 0xffff0000u); }

__device__ __forceinline__ void mma_bf16(float c[4], unsigned a0, unsigned a1,
                                         unsigned a2, unsigned a3,
                                         unsigned b0, unsigned b1) {
    asm volatile(
        "mma.sync.aligned.m16n8k16.row.col.f32.bf16.bf16.f32 "
        "{%0,%1,%2,%3},{%4,%5,%6,%7},{%8,%9},{%0,%1,%2,%3};"
        : "+f"(c[0]), "+f"(c[1]), "+f"(c[2]), "+f"(c[3])
        : "r"(a0), "r"(a1), "r"(a2), "r"(a3), "r"(b0), "r"(b1));
}

// ---- TMA bulk-copy + mbarrier helpers ----
__device__ __forceinline__ void mbar_init(unsigned mbar, unsigned count) {
    asm volatile("mbarrier.init.shared.b64 [%0], %1;" :: "r"(mbar), "r"(count) : "memory");
}
__device__ __forceinline__ void mbar_expect_tx(unsigned mbar, unsigned bytes) {
    asm volatile("mbarrier.arrive.expect_tx.shared.b64 _, [%0], %1;"
                 :: "r"(mbar), "r"(bytes) : "memory");
}
__device__ __forceinline__ void bulk_g2s(unsigned dst, const void* src,
                                         unsigned bytes, unsigned mbar) {
    asm volatile("cp.async.bulk.shared::cta.global.mbarrier::complete_tx::bytes "
                 "[%0], [%1], %2, [%3];"
                 :: "r"(dst), "l"(src), "r"(bytes), "r"(mbar) : "memory");
}
__device__ __forceinline__ void mbar_wait(unsigned mbar, int phase) {
    asm volatile(
        "{\n\t"
        ".reg .pred P;\n\t"
        "WAIT_%=:\n\t"
        "mbarrier.try_wait.parity.acquire.cta.shared::cta.b64 P, [%0], %1, 0x989680;\n\t"
        "@P bra DONE_%=;\n\t"
        "bra WAIT_%=;\n\t"
        "DONE_%=:\n\t"
        "}"
        :: "r"(mbar), "r"(phase) : "memory");
}

__device__ __forceinline__ void tile_fetch(unsigned dst_u32, const float* __restrict__ corpus,
                                           int tile, int N, unsigned mbar) {
    int docbase = tile * TILE_DOCS;
    int nd = min(TILE_DOCS, N - docbase);
    mbar_expect_tx(mbar, (unsigned)nd * 1536u);
    const float* src = corpus + (size_t)docbase * DIM;
    for (int d = 0; d < nd; d++)
        bulk_g2s(dst_u32 + d * (ROWP * 4), src + (size_t)d * DIM, 1536u, mbar);
}

// ---------------- launch 1: zero counters + query normalization ------------
__global__ void prep_kernel(const float* __restrict__ q, int M) {
    if (blockIdx.x < 16) {
        int row = blockIdx.x;
        if (row >= M) return;
        float ss = 0.f;
        for (int i = threadIdx.x; i < DIM; i += blockDim.x) {
            float v = q[row * DIM + i];
            ss += v * v;
        }
        __shared__ float red[256];
        red[threadIdx.x] = ss;
        __syncthreads();
        for (int s = 128; s > 0; s >>= 1) {
            if (threadIdx.x < s) red[threadIdx.x] += red[threadIdx.x + s];
            __syncthreads();
        }
        float inv = 1.f / fmaxf(sqrtf(red[0]), 1e-12f);
        for (int i = threadIdx.x; i < DIM; i += blockDim.x)
            g_qn[row * DIM + i] = q[row * DIM + i] * inv;
    } else {
        int i = (blockIdx.x - 16) * blockDim.x + threadIdx.x;   // 65536
        g_cnt[i] = 0;
        g_sum[i] = 0ull;
    }
}

// ---------------- launch 2: sims via split-bf16 mma.sync + TMA bulk --------
extern __shared__ float shf[];

__global__ void __launch_bounds__(SIM_TPB, 1)
sim_kernel(const float* __restrict__ corpus, float* __restrict__ sims,
           int M, int N) {
    uint4* tA    = (uint4*)(shf + OFF_TA);
    uint4* tB    = (uint4*)(shf + OFF_TB);
    float* part  = shf + OFF_PART;               // [half][d][17]
    float* invn  = shf + OFF_INV;                // [TILE_DOCS]
    unsigned smem_u32 = (unsigned)__cvta_generic_to_shared(shf);
    unsigned mbar0 = smem_u32 + OFF_MBAR * 4;
    unsigned mbar1 = mbar0 + 8;

    int tid  = threadIdx.x;
    int wid  = tid >> 5, lane = tid & 31;
    int g    = lane >> 2, tl = lane & 3;

    // build B fragment tables in SMEM (each warp: 3 hs values)
#pragma unroll
    for (int j = 0; j < 3; j++) {
        int hs = wid * 3 + j;                    // 0..23
        int h = hs / 12, s = hs - h * 12;
        int k0 = h * 192 + s * 16 + 2 * tl;
#pragma unroll
        for (int grp = 0; grp < 2; grp++) {
            const float* qp = g_qn + (grp * 8 + g) * DIM;
            float v00 = qp[k0],     v01 = qp[k0 + 1];
            float v10 = qp[k0 + 8], v11 = qp[k0 + 9];
            unsigned b0h = packbf(v00, v01);
            unsigned b1h = packbf(v10, v11);
            unsigned b0l = packbf(v00 - bflo(b0h), v01 - bfhi(b0h));
            unsigned b1l = packbf(v10 - bflo(b1h), v11 - bfhi(b1h));
            uint4 r = make_uint4(b0h, b1h, b0l, b1l);
            if (grp == 0) tA[hs * 32 + lane] = r;
            else          tB[hs * 32 + lane] = r;
        }
    }

    if (tid == 0) {
        mbar_init(mbar0, 1);
        mbar_init(mbar1, 1);
        asm volatile("fence.proxy.async.shared::cta;" ::: "memory");
    }
    __syncthreads();

    int ntiles = (N + TILE_DOCS - 1) / TILE_DOCS;
    if (tid == 0)
        tile_fetch(smem_u32 + OFF_TILES * 4, corpus, blockIdx.x, N, mbar0);

    int ph0 = 0, ph1 = 0;
    int it = 0;
    for (int t = blockIdx.x; t < ntiles; t += gridDim.x, it++) {
        int b = it & 1;
        float* cur = shf + OFF_TILES + b * TILE_F;
        int tn = t + gridDim.x;
        if (tid == 0 && tn < ntiles)
            tile_fetch(smem_u32 + (OFF_TILES + (b ^ 1) * TILE_F) * 4,
                       corpus, tn, N, b ? mbar0 : mbar1);
        // wait for current buffer (every thread waits individually)
        if (b == 0) { mbar_wait(mbar0, ph0); ph0 ^= 1; }
        else        { mbar_wait(mbar1, ph1); ph1 ^= 1; }

        int docbase = t * TILE_DOCS;

        if (wid < 6) {
            // MMA warp: doc-group dg (16 docs), K-half h (192 floats, 12 k16 steps)
            int dg = wid >> 1, h = wid & 1;
            const float* arow0 = cur + (dg * 16 + g) * ROWP;
            const float* arow8 = arow0 + 8 * ROWP;
            const uint4* fA = tA + (h * 12) * 32 + lane;
            const uint4* fB = tB + (h * 12) * 32 + lane;
            float c0[4] = {0.f, 0.f, 0.f, 0.f};   // queries 0-7
            float c1[4] = {0.f, 0.f, 0.f, 0.f};   // queries 8-15
            int kbase = h * 192 + 2 * tl;
#pragma unroll
            for (int s = 0; s < 12; s++) {
                int k = kbase + s * 16;
                float2 va0 = *(const float2*)(arow0 + k);
                float2 va1 = *(const float2*)(arow8 + k);
                float2 vb0 = *(const float2*)(arow0 + k + 8);
                float2 vb1 = *(const float2*)(arow8 + k + 8);
                unsigned ah0 = packbf(va0.x, va0.y);
                unsigned ah1 = packbf(va1.x, va1.y);
                unsigned ah2 = packbf(vb0.x, vb0.y);
                unsigned ah3 = packbf(vb1.x, vb1.y);
                unsigned al0 = packbf(va0.x - bflo(ah0), va0.y - bfhi(ah0));
                unsigned al1 = packbf(va1.x - bflo(ah1), va1.y - bfhi(ah1));
                unsigned al2 = packbf(vb0.x - bflo(ah2), vb0.y - bfhi(ah2));
                unsigned al3 = packbf(vb1.x - bflo(ah3), vb1.y - bfhi(ah3));
                uint4 B0 = fA[s * 32];
                uint4 B1 = fB[s * 32];
                mma_bf16(c0, ah0, ah1, ah2, ah3, B0.x, B0.y);   // ah*bh
                mma_bf16(c0, ah0, ah1, ah2, ah3, B0.z, B0.w);   // ah*bl
                mma_bf16(c0, al0, al1, al2, al3, B0.x, B0.y);   // al*bh
                mma_bf16(c1, ah0, ah1, ah2, ah3, B1.x, B1.y);
                mma_bf16(c1, ah0, ah1, ah2, ah3, B1.z, B1.w);
                mma_bf16(c1, al0, al1, al2, al3, B1.x, B1.y);
            }
            // write partials: part[h][d][q], stride 17
            float* pb = part + h * (TILE_DOCS * 17);
            int d0 = dg * 16 + g;
            pb[d0 * 17 + tl * 2]           = c0[0];
            pb[d0 * 17 + tl * 2 + 1]       = c0[1];
            pb[(d0 + 8) * 17 + tl * 2]     = c0[2];
            pb[(d0 + 8) * 17 + tl * 2 + 1] = c0[3];
            pb[d0 * 17 + 8 + tl * 2]           = c1[0];
            pb[d0 * 17 + 8 + tl * 2 + 1]       = c1[1];
            pb[(d0 + 8) * 17 + 8 + tl * 2]     = c1[2];
            pb[(d0 + 8) * 17 + 8 + tl * 2 + 1] = c1[3];
        } else {
            // norm warps: one doc per lane (exact fp32 norms)
            int d = (wid - 6) * 32 + lane;
            if (d < TILE_DOCS) {
                const float4* r4 = (const float4*)(cur + d * ROWP);
                float ss = 0.f;
#pragma unroll 8
                for (int i = 0; i < 96; i++) {
                    float4 v = r4[i];
                    ss += v.x * v.x + v.y * v.y + v.z * v.z + v.w * v.w;
                }
                invn[d] = 1.f / fmaxf(sqrtf(ss), 1e-12f);
            }
        }
        __syncthreads();

        // epilogue: combine halves, write sims + bucket aggregates
        for (int i = tid; i < TILE_DOCS * 16; i += SIM_TPB) {
            int qq = i / TILE_DOCS;
            int d  = i - qq * TILE_DOCS;
            int doc = docbase + d;
            if (doc < N && qq < M) {
                float v = (part[d * 17 + qq] + part[TILE_DOCS * 17 + d * 17 + qq])
                          * invn[d];
                sims[(size_t)qq * N + doc] = v;
                unsigned b2 = sortable(v) >> BSHIFT;
                atomicAdd(&g_cnt[qq * NB + b2], 1);
                long long fx = __double2ll_rn((double)v * FXS);
                atomicAdd(&g_sum[qq * NB + b2], (unsigned long long)fx);
            }
        }
        __syncthreads();   // all reads of buffer b done before its refill
    }
}

// ---------------- launch 3: bucket-level PAV, hierarchical merge ------------
__global__ void pavB_kernel(int N) {
    int row = blockIdx.x;
    int t = threadIdx.x;
    int lane = t & 31, ww = t >> 5;     // 8 warps
    extern __shared__ char sm[];
    double* ysum = (double*)sm;          // NB
    int*    cnt  = (int*)(ysum + NB);    // NB
    int*    bend = cnt + NB;             // NB
    __shared__ int snb[PAVB_TPB];
    __shared__ int wnb[8];
    __shared__ int sscan[PAVB_TPB];
    __shared__ int sP;

    // A: coalesced load of counts + z-sums
    for (int b = t; b < NB; b += PAVB_TPB) {
        cnt[b] = g_cnt[row * NB + b];
        ysum[b] = -10.0 * ((double)(long long)g_sum[row * NB + b] / FXS);
    }
    __syncthreads();

    // B: per-chunk counts + block-wide exclusive scan of positions
    int base = t * BPT;
    int lc[BPT];
    int tsum = 0;
#pragma unroll
    for (int e = 0; e < BPT; e++) { lc[e] = cnt[base + e]; tsum += lc[e]; }
    sscan[t] = tsum;
    __syncthreads();
    for (int off = 1; off < PAVB_TPB; off <<= 1) {
        int tv = (t >= off) ? sscan[t - off] : 0;
        __syncthreads();
        sscan[t] += tv;
        __syncthreads();
    }
    int run = sscan[t] - tsum;
#pragma unroll
    for (int e = 0; e < BPT; e++) {
        int c = lc[e];
        if (c) {
            ysum[base + e] -= ((double)c * (double)N - (double)c * (double)run
                               - (double)c * (double)(c - 1) * 0.5);
        }
        run += c;
    }

    // C: per-thread chunk PAV
    double lsum[BPT];
    int    lcn[BPT];
    int    lend[BPT];
    int p = 0;
#pragma unroll
    for (int e = 0; e < BPT; e++) {
        int cc = lc[e];
        if (!cc) continue;
        double cs = ysum[base + e];
        while (p > 0 && lsum[p - 1] * (double)cc < cs * (double)lcn[p - 1]) {
            cs += lsum[p - 1]; cc += lcn[p - 1]; p--;
        }
        lsum[p] = cs; lcn[p] = cc; lend[p] = base + e + 1; p++;
    }
    for (int k = 0; k < p; k++) {
        ysum[base + k] = lsum[k]; cnt[base + k] = lcn[k]; bend[base + k] = lend[k];
    }
    snb[t] = p;
    __syncthreads();

    // D: warp-leader merge of 32 chunk lists -> compacted at ww*512
    if (lane == 0) {
        int out = ww * 512;
        int P = 0;
        double TS = 0.0; int TC = 0, TE = 0;
        for (int c = ww * 32; c < ww * 32 + 32; c++) {
            int nb = snb[c];
            int bb = c * BPT;
            for (int k = 0; k < nb; k++) {
                double cs = ysum[bb + k];
                int cc = cnt[bb + k];
                int en = bend[bb + k];
                while (P > 0 && TS * (double)cc < cs * (double)TC) {
                    cs += TS; cc += TC; P--;
                    if (P > 0) { TS = ysum[out + P - 1]; TC = cnt[out + P - 1]; TE = bend[out + P - 1]; }
                }
                if (P > 0) { ysum[out + P - 1] = TS; cnt[out + P - 1] = TC; bend[out + P - 1] = TE; }
                TS = cs; TC = cc; TE = en; P++;
            }
        }
        if (P > 0) { ysum[out + P - 1] = TS; cnt[out + P - 1] = TC; bend[out + P - 1] = TE; }
        wnb[ww] = P;
    }
    __syncthreads();

    // E: thread 0 merges 8 warp lists -> final compacted at 0
    if (t == 0) {
        int P = 0;
        double TS = 0.0; int TC = 0, TE = 0;
        for (int w2 = 0; w2 < 8; w2++) {
            int nb = wnb[w2];
            int bb = w2 * 512;
            for (int k = 0; k < nb; k++) {
                double cs = ysum[bb + k];
                int cc = cnt[bb + k];
                int en = bend[bb + k];
                while (P > 0 && TS * (double)cc < cs * (double)TC) {
                    cs += TS; cc += TC; P--;
                    if (P > 0) { TS = ysum[P - 1]; TC = cnt[P - 1]; TE = bend[P - 1]; }
                }
                if (P > 0) { ysum[P - 1] = TS; cnt[P - 1] = TC; bend[P - 1] = TE; }
                TS = cs; TC = cc; TE = en; P++;
            }
        }
        if (P > 0) { ysum[P - 1] = TS; cnt[P - 1] = TC; bend[P - 1] = TE; }
        sP = P;
    }
    __syncthreads();

    // F: per-bucket dual (float) via binary search over block end-buckets
    int P = sP;
    for (int b = t; b < NB; b += PAVB_TPB) {
        int lo = 0, hi = P - 1;
        while (lo < hi) {
            int mid = (lo + hi) >> 1;
            if (bend[mid] > b) hi = mid; else lo = mid + 1;
        }
        g_dualf[row * NB + b] = (float)(ysum[lo] / (double)cnt[lo]);
    }
}

// ---------------- launch 4: rank output (pure fp32) -------------------------
__global__ void output_kernel(const float4* __restrict__ sims4,
                              float4* __restrict__ ranks4, int M, int N) {
    int i4 = blockIdx.x * blockDim.x + threadIdx.x;
    int total4 = (M * N) >> 2;
    if (i4 >= total4) return;
    int i = i4 * 4;
    int row = i / N;
    float4 v = sims4[i4];
    const float* dr = g_dualf + row * NB;
    float4 o;
    o.x = fmaf(-10.f, v.x, -dr[sortable(v.x) >> BSHIFT]);
    o.y = fmaf(-10.f, v.y, -dr[sortable(v.y) >> BSHIFT]);
    o.z = fmaf(-10.f, v.z, -dr[sortable(v.z) >> BSHIFT]);
    o.w = fmaf(-10.f, v.w, -dr[sortable(v.w) >> BSHIFT]);
    ranks4[i4] = o;
}

// ---------------- host launch ----------------
extern "C" void kernel_launch(void* const* d_in, const int* in_sizes, int n_in,
                              void* d_out, int out_size) {
    const float* q      = (const float*)d_in[0];
    const float* corpus = (const float*)d_in[1];
    int M = in_sizes[0] / DIM;   // 16
    int N = in_sizes[1] / DIM;   // 50000
    if (M > MAXM) M = MAXM;
    if (N > MAXN) N = MAXN;

    float* sims  = (float*)d_out;
    float* ranks = sims + (size_t)M * N;

    cudaFuncSetAttribute(sim_kernel,
                         cudaFuncAttributeMaxDynamicSharedMemorySize, SMEM_DYN);
    cudaFuncSetAttribute(pavB_kernel,
                         cudaFuncAttributeMaxDynamicSharedMemorySize, PAVB_SMEM);

    prep_kernel<<<16 + 256, 256>>>(q, M);                        // launch 1
    sim_kernel<<<SIM_BLOCKS, SIM_TPB, SMEM_DYN>>>(               // launch 2
        corpus, sims, M, N);
    pavB_kernel<<<M, PAVB_TPB, PAVB_SMEM>>>(N);                  // launch 3
    int total4 = (M * N) / 4;
    output_kernel<<<(total4 + 255) / 256, 256>>>(                // launch 4
        (const float4*)sims, (float4*)ranks, M, N);
}

// round 11
// speedup vs baseline: 1.3461x; 1.3461x over previous
#include <cuda_runtime.h>
#include <cstdint>

#define DIM   384
#define MAXM  16
#define MAXN  50000
#define NB    4096                 // buckets per row (top 12 bits of sortable key)
#define BSHIFT 20                  // 32 - 12
#define FXS   1099511627776.0      // 2^40 fixed-point scale

// ---- sim kernel geometry: 512 threads, 48-doc tiles, K split in quarters ---
#define TILE_DOCS 48
#define ROWP      388              // padded corpus row stride in floats
#define SIM_TPB   512
#define SIM_BLOCKS 148
#define BFRAG_U4  (2 * 12 * 32)                   // 768 uint4 per table (24 k16-steps)
#define OFF_TA    0
#define OFF_TB    (BFRAG_U4 * 4)                  // floats
#define OFF_TILES (2 * BFRAG_U4 * 4)              // 6144
#define TILE_F    (TILE_DOCS * ROWP)              // 18624
#define OFF_PART  (OFF_TILES + 2 * TILE_F)        // 43392
#define PART_F    (4 * TILE_DOCS * 17)            // 3264: [qtr][d][q] stride 17
#define OFF_INV   (OFF_PART + PART_F)             // 46656
#define SMEM_FLOATS (OFF_INV + TILE_DOCS)
#define SMEM_DYN  (SMEM_FLOATS * (int)sizeof(float))   // ~187 KB

#define PAVB_TPB 256
#define BPT (NB / PAVB_TPB)              // 16 buckets per thread
#define PAVB_SMEM (NB * (int)(sizeof(double) + 2 * sizeof(int)))   // 64 KB

// ---- static device scratch (no allocations allowed) ----
__device__ float              g_qn[MAXM * DIM];
__device__ int                g_cnt[MAXM * NB];
__device__ unsigned long long g_sum[MAXM * NB];
__device__ float              g_dualf[MAXM * NB];

__device__ __forceinline__ unsigned sortable(float f) {
    unsigned u = __float_as_uint(f);
    return (u & 0x80000000u) ? ~u : (u | 0x80000000u);   // ascending order
}

// pack two f32 -> bf16x2 (lo half = first arg, hi half = second arg)
__device__ __forceinline__ unsigned packbf(float lo, float hi) {
    unsigned r;
    asm("cvt.rn.bf16x2.f32 %0, %1, %2;" : "=r"(r) : "f"(hi), "f"(lo));
    return r;
}
__device__ __forceinline__ float bflo(unsigned u) { return __uint_as_float(u << 16); }
__device__ __forceinline__ float bfhi(unsigned u) { return __uint_as_float(u & 0xffff0000u); }

__device__ __forceinline__ void mma_bf16(float c[4], unsigned a0, unsigned a1,
                                         unsigned a2, unsigned a3,
                                         unsigned b0, unsigned b1) {
    asm volatile(
        "mma.sync.aligned.m16n8k16.row.col.f32.bf16.bf16.f32 "
        "{%0,%1,%2,%3},{%4,%5,%6,%7},{%8,%9},{%0,%1,%2,%3};"
        : "+f"(c[0]), "+f"(c[1]), "+f"(c[2]), "+f"(c[3])
        : "r"(a0), "r"(a1), "r"(a2), "r"(a3), "r"(b0), "r"(b1));
}

// ---- cp.async helpers ----
__device__ __forceinline__ void cp16(void* smem, const void* gmem) {
    unsigned s = (unsigned)__cvta_generic_to_shared(smem);
    asm volatile("cp.async.cg.shared.global [%0], [%1], 16;\n"
                 :: "r"(s), "l"(gmem) : "memory");
}
__device__ __forceinline__ void cp_commit() {
    asm volatile("cp.async.commit_group;\n" ::: "memory");
}
template <int W>
__device__ __forceinline__ void cp_wait() {
    asm volatile("cp.async.wait_group %0;\n" :: "n"(W) : "memory");
}

// ---------------- launch 1: zero counters + query normalization ------------
__global__ void prep_kernel(const float* __restrict__ q, int M) {
    if (blockIdx.x < 16) {
        int row = blockIdx.x;
        if (row >= M) return;
        float ss = 0.f;
        for (int i = threadIdx.x; i < DIM; i += blockDim.x) {
            float v = q[row * DIM + i];
            ss += v * v;
        }
        __shared__ float red[256];
        red[threadIdx.x] = ss;
        __syncthreads();
        for (int s = 128; s > 0; s >>= 1) {
            if (threadIdx.x < s) red[threadIdx.x] += red[threadIdx.x + s];
            __syncthreads();
        }
        float inv = 1.f / fmaxf(sqrtf(red[0]), 1e-12f);
        for (int i = threadIdx.x; i < DIM; i += blockDim.x)
            g_qn[row * DIM + i] = q[row * DIM + i] * inv;
    } else {
        int i = (blockIdx.x - 16) * blockDim.x + threadIdx.x;   // 65536
        g_cnt[i] = 0;
        g_sum[i] = 0ull;
    }
}

// ---------------- launch 2: sims via split-bf16 mma.sync, 16 warps ---------
extern __shared__ float shf[];

__global__ void __launch_bounds__(SIM_TPB, 1)
sim_kernel(const float4* __restrict__ corpus4, float* __restrict__ sims,
           int M, int N) {
    uint4* tA    = (uint4*)(shf + OFF_TA);
    uint4* tB    = (uint4*)(shf + OFF_TB);
    float* part  = shf + OFF_PART;               // [qtr][d][17]
    float* invn  = shf + OFF_INV;                // [TILE_DOCS]

    int tid  = threadIdx.x;
    int wid  = tid >> 5, lane = tid & 31;
    int g    = lane >> 2, tl = lane & 3;

    // build B fragment tables in SMEM (warps 0..11, 2 k16-steps each)
    if (wid < 12) {
#pragma unroll
        for (int j = 0; j < 2; j++) {
            int gs = wid * 2 + j;                // global k16 step 0..23
            int k0 = gs * 16 + 2 * tl;
#pragma unroll
            for (int grp = 0; grp < 2; grp++) {
                const float* qp = g_qn + (grp * 8 + g) * DIM;
                float v00 = qp[k0],     v01 = qp[k0 + 1];
                float v10 = qp[k0 + 8], v11 = qp[k0 + 9];
                unsigned b0h = packbf(v00, v01);
                unsigned b1h = packbf(v10, v11);
                unsigned b0l = packbf(v00 - bflo(b0h), v01 - bfhi(b0h));
                unsigned b1l = packbf(v10 - bflo(b1h), v11 - bfhi(b1h));
                uint4 r = make_uint4(b0h, b1h, b0l, b1l);
                if (grp == 0) tA[gs * 32 + lane] = r;
                else          tB[gs * 32 + lane] = r;
            }
        }
    }

    int ntiles = (N + TILE_DOCS - 1) / TILE_DOCS;

    // prefetch first tile (4608 float4, 9 per thread)
    {
        int docbase = blockIdx.x * TILE_DOCS;
        float4* dst = (float4*)(shf + OFF_TILES);
#pragma unroll
        for (int j = 0; j < 9; j++) {
            int idx = tid + j * SIM_TPB;
            int d = idx / 96, c = idx - d * 96;
            int doc = docbase + d;
            if (doc < N) cp16(dst + d * (ROWP / 4) + c, corpus4 + (size_t)doc * 96 + c);
        }
    }
    cp_commit();

    int it = 0;
    for (int t = blockIdx.x; t < ntiles; t += gridDim.x, it++) {
        float* cur = shf + OFF_TILES + (it & 1) * TILE_F;
        float* nxt = shf + OFF_TILES + ((it + 1) & 1) * TILE_F;
        int tn = t + gridDim.x;
        if (tn < ntiles) {
            int docbase = tn * TILE_DOCS;
            float4* dst = (float4*)nxt;
#pragma unroll
            for (int j = 0; j < 9; j++) {
                int idx = tid + j * SIM_TPB;
                int d = idx / 96, c = idx - d * 96;
                int doc = docbase + d;
                if (doc < N) cp16(dst + d * (ROWP / 4) + c, corpus4 + (size_t)doc * 96 + c);
            }
            cp_commit();
            cp_wait<1>();
        } else {
            cp_wait<0>();
        }
        __syncthreads();

        int docbase = t * TILE_DOCS;

        if (wid < 12) {
            // MMA warp: doc-group dg (16 docs), K-quarter qtr (96 floats, 6 k16 steps)
            int dg = wid >> 2, qtr = wid & 3;
            const float* arow0 = cur + (dg * 16 + g) * ROWP;
            const float* arow8 = arow0 + 8 * ROWP;
            int gs0 = qtr * 6;
            const uint4* fA = tA + gs0 * 32 + lane;
            const uint4* fB = tB + gs0 * 32 + lane;
            float c0[4] = {0.f, 0.f, 0.f, 0.f};   // queries 0-7
            float c1[4] = {0.f, 0.f, 0.f, 0.f};   // queries 8-15
            int kbase = qtr * 96 + 2 * tl;
#pragma unroll
            for (int s = 0; s < 6; s++) {
                int k = kbase + s * 16;
                float2 va0 = *(const float2*)(arow0 + k);
                float2 va1 = *(const float2*)(arow8 + k);
                float2 vb0 = *(const float2*)(arow0 + k + 8);
                float2 vb1 = *(const float2*)(arow8 + k + 8);
                unsigned ah0 = packbf(va0.x, va0.y);
                unsigned ah1 = packbf(va1.x, va1.y);
                unsigned ah2 = packbf(vb0.x, vb0.y);
                unsigned ah3 = packbf(vb1.x, vb1.y);
                unsigned al0 = packbf(va0.x - bflo(ah0), va0.y - bfhi(ah0));
                unsigned al1 = packbf(va1.x - bflo(ah1), va1.y - bfhi(ah1));
                unsigned al2 = packbf(vb0.x - bflo(ah2), vb0.y - bfhi(ah2));
                unsigned al3 = packbf(vb1.x - bflo(ah3), vb1.y - bfhi(ah3));
                uint4 B0 = fA[s * 32];
                uint4 B1 = fB[s * 32];
                mma_bf16(c0, ah0, ah1, ah2, ah3, B0.x, B0.y);   // ah*bh
                mma_bf16(c0, ah0, ah1, ah2, ah3, B0.z, B0.w);   // ah*bl
                mma_bf16(c0, al0, al1, al2, al3, B0.x, B0.y);   // al*bh
                mma_bf16(c1, ah0, ah1, ah2, ah3, B1.x, B1.y);
                mma_bf16(c1, ah0, ah1, ah2, ah3, B1.z, B1.w);
                mma_bf16(c1, al0, al1, al2, al3, B1.x, B1.y);
            }
            // write partials: part[qtr][d][q], stride 17
            float* pb = part + qtr * (TILE_DOCS * 17);
            int d0 = dg * 16 + g;
            pb[d0 * 17 + tl * 2]           = c0[0];
            pb[d0 * 17 + tl * 2 + 1]       = c0[1];
            pb[(d0 + 8) * 17 + tl * 2]     = c0[2];
            pb[(d0 + 8) * 17 + tl * 2 + 1] = c0[3];
            pb[d0 * 17 + 8 + tl * 2]           = c1[0];
            pb[d0 * 17 + 8 + tl * 2 + 1]       = c1[1];
            pb[(d0 + 8) * 17 + 8 + tl * 2]     = c1[2];
            pb[(d0 + 8) * 17 + 8 + tl * 2 + 1] = c1[3];
        } else if (wid < 14) {
            // norm warps 12,13: one doc per lane (exact fp32 norms)
            int d = (wid - 12) * 32 + lane;
            if (d < TILE_DOCS) {
                const float4* r4 = (const float4*)(cur + d * ROWP);
                float ss = 0.f;
#pragma unroll 8
                for (int i = 0; i < 96; i++) {
                    float4 v = r4[i];
                    ss += v.x * v.x + v.y * v.y + v.z * v.z + v.w * v.w;
                }
                invn[d] = 1.f / fmaxf(sqrtf(ss), 1e-12f);
            }
        }
        __syncthreads();

        // epilogue: combine 4 quarters, write sims + bucket aggregates
        for (int i = tid; i < TILE_DOCS * 16; i += SIM_TPB) {
            int qq = i / TILE_DOCS;
            int d  = i - qq * TILE_DOCS;
            int doc = docbase + d;
            if (doc < N && qq < M) {
                float v = (part[d * 17 + qq]
                         + part[TILE_DOCS * 17 + d * 17 + qq]
                         + part[2 * TILE_DOCS * 17 + d * 17 + qq]
                         + part[3 * TILE_DOCS * 17 + d * 17 + qq]) * invn[d];
                sims[(size_t)qq * N + doc] = v;
                unsigned b2 = sortable(v) >> BSHIFT;
                atomicAdd(&g_cnt[qq * NB + b2], 1);
                long long fx = __double2ll_rn((double)v * FXS);
                atomicAdd(&g_sum[qq * NB + b2], (unsigned long long)fx);
            }
        }
        __syncthreads();   // before buffer reuse
    }
}

// ---------------- launch 3: bucket-level PAV, hierarchical merge ------------
__global__ void pavB_kernel(int N) {
    int row = blockIdx.x;
    int t = threadIdx.x;
    int lane = t & 31, ww = t >> 5;     // 8 warps
    extern __shared__ char sm[];
    double* ysum = (double*)sm;          // NB
    int*    cnt  = (int*)(ysum + NB);    // NB
    int*    bend = cnt + NB;             // NB
    __shared__ int snb[PAVB_TPB];
    __shared__ int wnb[8];
    __shared__ int sscan[PAVB_TPB];
    __shared__ int sP;

    // A: coalesced load of counts + z-sums
    for (int b = t; b < NB; b += PAVB_TPB) {
        cnt[b] = g_cnt[row * NB + b];
        ysum[b] = -10.0 * ((double)(long long)g_sum[row * NB + b] / FXS);
    }
    __syncthreads();

    // B: per-chunk counts + block-wide exclusive scan of positions
    int base = t * BPT;
    int lc[BPT];
    int tsum = 0;
#pragma unroll
    for (int e = 0; e < BPT; e++) { lc[e] = cnt[base + e]; tsum += lc[e]; }
    sscan[t] = tsum;
    __syncthreads();
    for (int off = 1; off < PAVB_TPB; off <<= 1) {
        int tv = (t >= off) ? sscan[t - off] : 0;
        __syncthreads();
        sscan[t] += tv;
        __syncthreads();
    }
    int run = sscan[t] - tsum;
#pragma unroll
    for (int e = 0; e < BPT; e++) {
        int c = lc[e];
        if (c) {
            ysum[base + e] -= ((double)c * (double)N - (double)c * (double)run
                               - (double)c * (double)(c - 1) * 0.5);
        }
        run += c;
    }

    // C: per-thread chunk PAV
    double lsum[BPT];
    int    lcn[BPT];
    int    lend[BPT];
    int p = 0;
#pragma unroll
    for (int e = 0; e < BPT; e++) {
        int cc = lc[e];
        if (!cc) continue;
        double cs = ysum[base + e];
        while (p > 0 && lsum[p - 1] * (double)cc < cs * (double)lcn[p - 1]) {
            cs += lsum[p - 1]; cc += lcn[p - 1]; p--;
        }
        lsum[p] = cs; lcn[p] = cc; lend[p] = base + e + 1; p++;
    }
    for (int k = 0; k < p; k++) {
        ysum[base + k] = lsum[k]; cnt[base + k] = lcn[k]; bend[base + k] = lend[k];
    }
    snb[t] = p;
    __syncthreads();

    // D: warp-leader merge of 32 chunk lists -> compacted at ww*512
    if (lane == 0) {
        int out = ww * 512;
        int P = 0;
        double TS = 0.0; int TC = 0, TE = 0;
        for (int c = ww * 32; c < ww * 32 + 32; c++) {
            int nb = snb[c];
            int bb = c * BPT;
            for (int k = 0; k < nb; k++) {
                double cs = ysum[bb + k];
                int cc = cnt[bb + k];
                int en = bend[bb + k];
                while (P > 0 && TS * (double)cc < cs * (double)TC) {
                    cs += TS; cc += TC; P--;
                    if (P > 0) { TS = ysum[out + P - 1]; TC = cnt[out + P - 1]; TE = bend[out + P - 1]; }
                }
                if (P > 0) { ysum[out + P - 1] = TS; cnt[out + P - 1] = TC; bend[out + P - 1] = TE; }
                TS = cs; TC = cc; TE = en; P++;
            }
        }
        if (P > 0) { ysum[out + P - 1] = TS; cnt[out + P - 1] = TC; bend[out + P - 1] = TE; }
        wnb[ww] = P;
    }
    __syncthreads();

    // E: thread 0 merges 8 warp lists -> final compacted at 0
    if (t == 0) {
        int P = 0;
        double TS = 0.0; int TC = 0, TE = 0;
        for (int w2 = 0; w2 < 8; w2++) {
            int nb = wnb[w2];
            int bb = w2 * 512;
            for (int k = 0; k < nb; k++) {
                double cs = ysum[bb + k];
                int cc = cnt[bb + k];
                int en = bend[bb + k];
                while (P > 0 && TS * (double)cc < cs * (double)TC) {
                    cs += TS; cc += TC; P--;
                    if (P > 0) { TS = ysum[P - 1]; TC = cnt[P - 1]; TE = bend[P - 1]; }
                }
                if (P > 0) { ysum[P - 1] = TS; cnt[P - 1] = TC; bend[P - 1] = TE; }
                TS = cs; TC = cc; TE = en; P++;
            }
        }
        if (P > 0) { ysum[P - 1] = TS; cnt[P - 1] = TC; bend[P - 1] = TE; }
        sP = P;
    }
    __syncthreads();

    // F: per-bucket dual (float) via binary search over block end-buckets
    int P = sP;
    for (int b = t; b < NB; b += PAVB_TPB) {
        int lo = 0, hi = P - 1;
        while (lo < hi) {
            int mid = (lo + hi) >> 1;
            if (bend[mid] > b) hi = mid; else lo = mid + 1;
        }
        g_dualf[row * NB + b] = (float)(ysum[lo] / (double)cnt[lo]);
    }
}

// ---------------- launch 4: rank output (pure fp32) -------------------------
__global__ void output_kernel(const float4* __restrict__ sims4,
                              float4* __restrict__ ranks4, int M, int N) {
    int i4 = blockIdx.x * blockDim.x + threadIdx.x;
    int total4 = (M * N) >> 2;
    if (i4 >= total4) return;
    int i = i4 * 4;
    int row = i / N;
    float4 v = sims4[i4];
    const float* dr = g_dualf + row * NB;
    float4 o;
    o.x = fmaf(-10.f, v.x, -dr[sortable(v.x) >> BSHIFT]);
    o.y = fmaf(-10.f, v.y, -dr[sortable(v.y) >> BSHIFT]);
    o.z = fmaf(-10.f, v.z, -dr[sortable(v.z) >> BSHIFT]);
    o.w = fmaf(-10.f, v.w, -dr[sortable(v.w) >> BSHIFT]);
    ranks4[i4] = o;
}

// ---------------- host launch ----------------
extern "C" void kernel_launch(void* const* d_in, const int* in_sizes, int n_in,
                              void* d_out, int out_size) {
    const float* q      = (const float*)d_in[0];
    const float* corpus = (const float*)d_in[1];
    int M = in_sizes[0] / DIM;   // 16
    int N = in_sizes[1] / DIM;   // 50000
    if (M > MAXM) M = MAXM;
    if (N > MAXN) N = MAXN;

    float* sims  = (float*)d_out;
    float* ranks = sims + (size_t)M * N;

    cudaFuncSetAttribute(sim_kernel,
                         cudaFuncAttributeMaxDynamicSharedMemorySize, SMEM_DYN);
    cudaFuncSetAttribute(pavB_kernel,
                         cudaFuncAttributeMaxDynamicSharedMemorySize, PAVB_SMEM);

    prep_kernel<<<16 + 256, 256>>>(q, M);                        // launch 1
    sim_kernel<<<SIM_BLOCKS, SIM_TPB, SMEM_DYN>>>(               // launch 2
        (const float4*)corpus, sims, M, N);
    pavB_kernel<<<M, PAVB_TPB, PAVB_SMEM>>>(N);                  // launch 3
    int total4 = (M * N) / 4;
    output_kernel<<<(total4 + 255) / 256, 256>>>(                // launch 4
        (const float4*)sims, (float4*)ranks, M, N);
}

// round 12
// speedup vs baseline: 1.4950x; 1.1106x over previous
#include <cuda_runtime.h>
#include <cstdint>

#define DIM   384
#define MAXM  16
#define MAXN  50000
#define NB    4096                 // buckets per row (top 12 bits of sortable key)
#define BSHIFT 20                  // 32 - 12

// fused atomic encoding: contribution = (1<<48) + (v*2^24 + 2^25)
#define VSCALE 16777216.0          // 2^24
#define VBIAS  33554432.0          // 2^25

// ---- sim kernel geometry: 256 threads, 48-doc tiles, K halves -------------
#define TILE_DOCS 48
#define ROWP      388              // padded corpus row stride in floats
#define SIM_TPB   256
#define SIM_BLOCKS 148
#define BFRAG_U4  (2 * 12 * 32)                   // 768 uint4 per table (24 k16-steps)
#define OFF_TA    0
#define OFF_TB    (BFRAG_U4 * 4)
#define OFF_TILES (2 * BFRAG_U4 * 4)              // 6144
#define TILE_F    (TILE_DOCS * ROWP)              // 18624
#define OFF_PART  (OFF_TILES + 2 * TILE_F)        // 43392
#define PART_F    (2 * TILE_DOCS * 17)            // 1632: [half][d][q] stride 17
#define OFF_NP    (OFF_PART + PART_F)             // 45024: [half][48] norm partials
#define SMEM_FLOATS (OFF_NP + 2 * TILE_DOCS)
#define SMEM_DYN  (SMEM_FLOATS * (int)sizeof(float))   // ~180 KB

#define PAVB_TPB 256
#define BPT (NB / PAVB_TPB)              // 16 buckets per thread
#define PAVB_SMEM (NB * (int)(sizeof(double) + 2 * sizeof(int)))   // 64 KB

// ---- static device scratch (no allocations allowed) ----
__device__ float              g_qn[MAXM * DIM];
__device__ unsigned long long g_sum[MAXM * NB];   // fused {count:16 | biased fx sum:48}
__device__ float              g_dualf[MAXM * NB];

__device__ __forceinline__ unsigned sortable(float f) {
    unsigned u = __float_as_uint(f);
    return (u & 0x80000000u) ? ~u : (u | 0x80000000u);   // ascending order
}

// pack two f32 -> bf16x2
__device__ __forceinline__ unsigned packbf(float lo, float hi) {
    unsigned r;
    asm("cvt.rn.bf16x2.f32 %0, %1, %2;" : "=r"(r) : "f"(hi), "f"(lo));
    return r;
}
__device__ __forceinline__ float bflo(unsigned u) { return __uint_as_float(u << 16); }
__device__ __forceinline__ float bfhi(unsigned u) { return __uint_as_float(u & 0xffff0000u); }

__device__ __forceinline__ void mma_bf16(float c[4], unsigned a0, unsigned a1,
                                         unsigned a2, unsigned a3,
                                         unsigned b0, unsigned b1) {
    asm volatile(
        "mma.sync.aligned.m16n8k16.row.col.f32.bf16.bf16.f32 "
        "{%0,%1,%2,%3},{%4,%5,%6,%7},{%8,%9},{%0,%1,%2,%3};"
        : "+f"(c[0]), "+f"(c[1]), "+f"(c[2]), "+f"(c[3])
        : "r"(a0), "r"(a1), "r"(a2), "r"(a3), "r"(b0), "r"(b1));
}

// ---- cp.async helpers ----
__device__ __forceinline__ void cp16(void* smem, const void* gmem) {
    unsigned s = (unsigned)__cvta_generic_to_shared(smem);
    asm volatile("cp.async.cg.shared.global [%0], [%1], 16;\n"
                 :: "r"(s), "l"(gmem) : "memory");
}
__device__ __forceinline__ void cp_commit() {
    asm volatile("cp.async.commit_group;\n" ::: "memory");
}
template <int W>
__device__ __forceinline__ void cp_wait() {
    asm volatile("cp.async.wait_group %0;\n" :: "n"(W) : "memory");
}

// ---------------- launch 1: zero fused sums + query normalization ----------
__global__ void prep_kernel(const float* __restrict__ q, int M) {
    if (blockIdx.x < 16) {
        int row = blockIdx.x;
        if (row >= M) return;
        float ss = 0.f;
        for (int i = threadIdx.x; i < DIM; i += blockDim.x) {
            float v = q[row * DIM + i];
            ss += v * v;
        }
        __shared__ float red[256];
        red[threadIdx.x] = ss;
        __syncthreads();
        for (int s = 128; s > 0; s >>= 1) {
            if (threadIdx.x < s) red[threadIdx.x] += red[threadIdx.x + s];
            __syncthreads();
        }
        float inv = 1.f / fmaxf(sqrtf(red[0]), 1e-12f);
        for (int i = threadIdx.x; i < DIM; i += blockDim.x)
            g_qn[row * DIM + i] = q[row * DIM + i] * inv;
    } else {
        int i = (blockIdx.x - 16) * blockDim.x + threadIdx.x;   // 65536
        g_sum[i] = 0ull;
    }
}

// ---------------- launch 2: sims via split-bf16 mma.sync + fused norms -----
extern __shared__ float shf[];

__global__ void __launch_bounds__(SIM_TPB, 1)
sim_kernel(const float4* __restrict__ corpus4, float* __restrict__ sims,
           int M, int N) {
    uint4* tA    = (uint4*)(shf + OFF_TA);
    uint4* tB    = (uint4*)(shf + OFF_TB);
    float* part  = shf + OFF_PART;               // [half][d][17]
    float* npart = shf + OFF_NP;                 // [half][48]

    int tid  = threadIdx.x;
    int wid  = tid >> 5, lane = tid & 31;
    int g    = lane >> 2, tl = lane & 3;

    // build B fragment tables in SMEM (each warp: 3 k16-steps)
#pragma unroll
    for (int j = 0; j < 3; j++) {
        int gs = wid * 3 + j;                    // 0..23
        int k0 = gs * 16 + 2 * tl;
#pragma unroll
        for (int grp = 0; grp < 2; grp++) {
            const float* qp = g_qn + (grp * 8 + g) * DIM;
            float v00 = qp[k0],     v01 = qp[k0 + 1];
            float v10 = qp[k0 + 8], v11 = qp[k0 + 9];
            unsigned b0h = packbf(v00, v01);
            unsigned b1h = packbf(v10, v11);
            unsigned b0l = packbf(v00 - bflo(b0h), v01 - bfhi(b0h));
            unsigned b1l = packbf(v10 - bflo(b1h), v11 - bfhi(b1h));
            uint4 r = make_uint4(b0h, b1h, b0l, b1l);
            if (grp == 0) tA[gs * 32 + lane] = r;
            else          tB[gs * 32 + lane] = r;
        }
    }

    int ntiles = (N + TILE_DOCS - 1) / TILE_DOCS;

    // prefetch first tile (4608 float4, 18 per thread)
    {
        int docbase = blockIdx.x * TILE_DOCS;
        float4* dst = (float4*)(shf + OFF_TILES);
#pragma unroll
        for (int j = 0; j < 18; j++) {
            int idx = tid + j * SIM_TPB;
            int d = idx / 96, c = idx - d * 96;
            int doc = docbase + d;
            if (doc < N) cp16(dst + d * (ROWP / 4) + c, corpus4 + (size_t)doc * 96 + c);
        }
    }
    cp_commit();

    int it = 0;
    for (int t = blockIdx.x; t < ntiles; t += gridDim.x, it++) {
        float* cur = shf + OFF_TILES + (it & 1) * TILE_F;
        float* nxt = shf + OFF_TILES + ((it + 1) & 1) * TILE_F;
        int tn = t + gridDim.x;
        if (tn < ntiles) {
            int docbase = tn * TILE_DOCS;
            float4* dst = (float4*)nxt;
#pragma unroll
            for (int j = 0; j < 18; j++) {
                int idx = tid + j * SIM_TPB;
                int d = idx / 96, c = idx - d * 96;
                int doc = docbase + d;
                if (doc < N) cp16(dst + d * (ROWP / 4) + c, corpus4 + (size_t)doc * 96 + c);
            }
            cp_commit();
            cp_wait<1>();
        } else {
            cp_wait<0>();
        }
        __syncthreads();

        int docbase = t * TILE_DOCS;

        if (wid < 6) {
            // MMA warp: doc-group dg (16 docs), K-half h (192 floats, 12 k16 steps)
            int dg = wid >> 1, h = wid & 1;
            const float* arow0 = cur + (dg * 16 + g) * ROWP;
            const float* arow8 = arow0 + 8 * ROWP;
            const uint4* fA = tA + (h * 12) * 32 + lane;
            const uint4* fB = tB + (h * 12) * 32 + lane;
            // split accumulators: main (ah*bh) + cross (ah*bl + al*bh)
            float m0[4] = {0.f, 0.f, 0.f, 0.f};
            float x0[4] = {0.f, 0.f, 0.f, 0.f};
            float m1[4] = {0.f, 0.f, 0.f, 0.f};
            float x1[4] = {0.f, 0.f, 0.f, 0.f};
            float ss0 = 0.f, ss1 = 0.f;          // per-lane norm partials, rows g / g+8
            int kbase = h * 192 + 2 * tl;
#pragma unroll
            for (int s = 0; s < 12; s++) {
                int k = kbase + s * 16;
                float2 va0 = *(const float2*)(arow0 + k);
                float2 va1 = *(const float2*)(arow8 + k);
                float2 vb0 = *(const float2*)(arow0 + k + 8);
                float2 vb1 = *(const float2*)(arow8 + k + 8);
                ss0 += va0.x * va0.x + va0.y * va0.y + vb0.x * vb0.x + vb0.y * vb0.y;
                ss1 += va1.x * va1.x + va1.y * va1.y + vb1.x * vb1.x + vb1.y * vb1.y;
                unsigned ah0 = packbf(va0.x, va0.y);
                unsigned ah1 = packbf(va1.x, va1.y);
                unsigned ah2 = packbf(vb0.x, vb0.y);
                unsigned ah3 = packbf(vb1.x, vb1.y);
                unsigned al0 = packbf(va0.x - bflo(ah0), va0.y - bfhi(ah0));
                unsigned al1 = packbf(va1.x - bflo(ah1), va1.y - bfhi(ah1));
                unsigned al2 = packbf(vb0.x - bflo(ah2), vb0.y - bfhi(ah2));
                unsigned al3 = packbf(vb1.x - bflo(ah3), vb1.y - bfhi(ah3));
                uint4 B0 = fA[s * 32];
                uint4 B1 = fB[s * 32];
                mma_bf16(m0, ah0, ah1, ah2, ah3, B0.x, B0.y);   // ah*bh
                mma_bf16(x0, ah0, ah1, ah2, ah3, B0.z, B0.w);   // ah*bl
                mma_bf16(x0, al0, al1, al2, al3, B0.x, B0.y);   // al*bh
                mma_bf16(m1, ah0, ah1, ah2, ah3, B1.x, B1.y);
                mma_bf16(x1, ah0, ah1, ah2, ah3, B1.z, B1.w);
                mma_bf16(x1, al0, al1, al2, al3, B1.x, B1.y);
            }
            // reduce norm partials over the 4-lane tl group
            ss0 += __shfl_xor_sync(0xffffffffu, ss0, 1);
            ss0 += __shfl_xor_sync(0xffffffffu, ss0, 2);
            ss1 += __shfl_xor_sync(0xffffffffu, ss1, 1);
            ss1 += __shfl_xor_sync(0xffffffffu, ss1, 2);
            int d0 = dg * 16 + g;
            if (tl == 0) {
                npart[h * TILE_DOCS + d0]     = ss0;
                npart[h * TILE_DOCS + d0 + 8] = ss1;
            }
            // write partials: part[h][d][q], stride 17
            float* pb = part + h * (TILE_DOCS * 17);
            pb[d0 * 17 + tl * 2]           = m0[0] + x0[0];
            pb[d0 * 17 + tl * 2 + 1]       = m0[1] + x0[1];
            pb[(d0 + 8) * 17 + tl * 2]     = m0[2] + x0[2];
            pb[(d0 + 8) * 17 + tl * 2 + 1] = m0[3] + x0[3];
            pb[d0 * 17 + 8 + tl * 2]           = m1[0] + x1[0];
            pb[d0 * 17 + 8 + tl * 2 + 1]       = m1[1] + x1[1];
            pb[(d0 + 8) * 17 + 8 + tl * 2]     = m1[2] + x1[2];
            pb[(d0 + 8) * 17 + 8 + tl * 2 + 1] = m1[3] + x1[3];
        }
        __syncthreads();

        // epilogue: combine halves + norms, write sims + ONE fused atomic
        for (int i = tid; i < TILE_DOCS * 16; i += SIM_TPB) {
            int qq = i / TILE_DOCS;
            int d  = i - qq * TILE_DOCS;
            int doc = docbase + d;
            if (doc < N && qq < M) {
                float n2 = npart[d] + npart[TILE_DOCS + d];
                float v = (part[d * 17 + qq] + part[TILE_DOCS * 17 + d * 17 + qq])
                          * rsqrtf(fmaxf(n2, 1e-24f));
                sims[(size_t)qq * N + doc] = v;
                unsigned b2 = sortable(v) >> BSHIFT;
                long long fx = __double2ll_rn((double)v * VSCALE + VBIAS);
                atomicAdd(&g_sum[qq * NB + b2],
                          (1ull << 48) + (unsigned long long)fx);
            }
        }
        __syncthreads();   // before buffer reuse
    }
}

// ---------------- launch 3: bucket-level PAV, hierarchical merge ------------
__global__ void pavB_kernel(int N) {
    int row = blockIdx.x;
    int t = threadIdx.x;
    int lane = t & 31, ww = t >> 5;     // 8 warps
    extern __shared__ char sm[];
    double* ysum = (double*)sm;          // NB
    int*    cnt  = (int*)(ysum + NB);    // NB
    int*    bend = cnt + NB;             // NB
    __shared__ int snb[PAVB_TPB];
    __shared__ int wnb[8];
    __shared__ int sscan[PAVB_TPB];
    __shared__ int sP;

    // A: coalesced load + decode of fused sums
    for (int b = t; b < NB; b += PAVB_TPB) {
        unsigned long long s = g_sum[row * NB + b];
        int c = (int)(s >> 48);
        double raw = (double)(s & 0xFFFFFFFFFFFFull);
        cnt[b] = c;
        // sum(v) = (raw - c*VBIAS)/VSCALE ; ysum = -10*sum(v)
        ysum[b] = -10.0 * ((raw - (double)c * VBIAS) / VSCALE);
    }
    __syncthreads();

    // B: per-chunk counts + block-wide exclusive scan of positions
    int base = t * BPT;
    int lc[BPT];
    int tsum = 0;
#pragma unroll
    for (int e = 0; e < BPT; e++) { lc[e] = cnt[base + e]; tsum += lc[e]; }
    sscan[t] = tsum;
    __syncthreads();
    for (int off = 1; off < PAVB_TPB; off <<= 1) {
        int tv = (t >= off) ? sscan[t - off] : 0;
        __syncthreads();
        sscan[t] += tv;
        __syncthreads();
    }
    int run = sscan[t] - tsum;
#pragma unroll
    for (int e = 0; e < BPT; e++) {
        int c = lc[e];
        if (c) {
            ysum[base + e] -= ((double)c * (double)N - (double)c * (double)run
                               - (double)c * (double)(c - 1) * 0.5);
        }
        run += c;
    }

    // C: per-thread chunk PAV
    double lsum[BPT];
    int    lcn[BPT];
    int    lend[BPT];
    int p = 0;
#pragma unroll
    for (int e = 0; e < BPT; e++) {
        int cc = lc[e];
        if (!cc) continue;
        double cs = ysum[base + e];
        while (p > 0 && lsum[p - 1] * (double)cc < cs * (double)lcn[p - 1]) {
            cs += lsum[p - 1]; cc += lcn[p - 1]; p--;
        }
        lsum[p] = cs; lcn[p] = cc; lend[p] = base + e + 1; p++;
    }
    for (int k = 0; k < p; k++) {
        ysum[base + k] = lsum[k]; cnt[base + k] = lcn[k]; bend[base + k] = lend[k];
    }
    snb[t] = p;
    __syncthreads();

    // D: warp-leader merge of 32 chunk lists -> compacted at ww*512
    if (lane == 0) {
        int out = ww * 512;
        int P = 0;
        double TS = 0.0; int TC = 0, TE = 0;
        for (int c = ww * 32; c < ww * 32 + 32; c++) {
            int nb = snb[c];
            int bb = c * BPT;
            for (int k = 0; k < nb; k++) {
                double cs = ysum[bb + k];
                int cc = cnt[bb + k];
                int en = bend[bb + k];
                while (P > 0 && TS * (double)cc < cs * (double)TC) {
                    cs += TS; cc += TC; P--;
                    if (P > 0) { TS = ysum[out + P - 1]; TC = cnt[out + P - 1]; TE = bend[out + P - 1]; }
                }
                if (P > 0) { ysum[out + P - 1] = TS; cnt[out + P - 1] = TC; bend[out + P - 1] = TE; }
                TS = cs; TC = cc; TE = en; P++;
            }
        }
        if (P > 0) { ysum[out + P - 1] = TS; cnt[out + P - 1] = TC; bend[out + P - 1] = TE; }
        wnb[ww] = P;
    }
    __syncthreads();

    // E: thread 0 merges 8 warp lists -> final compacted at 0
    if (t == 0) {
        int P = 0;
        double TS = 0.0; int TC = 0, TE = 0;
        for (int w2 = 0; w2 < 8; w2++) {
            int nb = wnb[w2];
            int bb = w2 * 512;
            for (int k = 0; k < nb; k++) {
                double cs = ysum[bb + k];
                int cc = cnt[bb + k];
                int en = bend[bb + k];
                while (P > 0 && TS * (double)cc < cs * (double)TC) {
                    cs += TS; cc += TC; P--;
                    if (P > 0) { TS = ysum[P - 1]; TC = cnt[P - 1]; TE = bend[P - 1]; }
                }
                if (P > 0) { ysum[P - 1] = TS; cnt[P - 1] = TC; bend[P - 1] = TE; }
                TS = cs; TC = cc; TE = en; P++;
            }
        }
        if (P > 0) { ysum[P - 1] = TS; cnt[P - 1] = TC; bend[P - 1] = TE; }
        sP = P;
    }
    __syncthreads();

    // F: per-bucket dual (float) via binary search over block end-buckets
    int P = sP;
    for (int b = t; b < NB; b += PAVB_TPB) {
        int lo = 0, hi = P - 1;
        while (lo < hi) {
            int mid = (lo + hi) >> 1;
            if (bend[mid] > b) hi = mid; else lo = mid + 1;
        }
        g_dualf[row * NB + b] = (float)(ysum[lo] / (double)cnt[lo]);
    }
}

// ---------------- launch 4: rank output (pure fp32) -------------------------
__global__ void output_kernel(const float4* __restrict__ sims4,
                              float4* __restrict__ ranks4, int M, int N) {
    int i4 = blockIdx.x * blockDim.x + threadIdx.x;
    int total4 = (M * N) >> 2;
    if (i4 >= total4) return;
    int i = i4 * 4;
    int row = i / N;
    float4 v = sims4[i4];
    const float* dr = g_dualf + row * NB;
    float4 o;
    o.x = fmaf(-10.f, v.x, -dr[sortable(v.x) >> BSHIFT]);
    o.y = fmaf(-10.f, v.y, -dr[sortable(v.y) >> BSHIFT]);
    o.z = fmaf(-10.f, v.z, -dr[sortable(v.z) >> BSHIFT]);
    o.w = fmaf(-10.f, v.w, -dr[sortable(v.w) >> BSHIFT]);
    ranks4[i4] = o;
}

// ---------------- host launch ----------------
extern "C" void kernel_launch(void* const* d_in, const int* in_sizes, int n_in,
                              void* d_out, int out_size) {
    const float* q      = (const float*)d_in[0];
    const float* corpus = (const float*)d_in[1];
    int M = in_sizes[0] / DIM;   // 16
    int N = in_sizes[1] / DIM;   // 50000
    if (M > MAXM) M = MAXM;
    if (N > MAXN) N = MAXN;

    float* sims  = (float*)d_out;
    float* ranks = sims + (size_t)M * N;

    cudaFuncSetAttribute(sim_kernel,
                         cudaFuncAttributeMaxDynamicSharedMemorySize, SMEM_DYN);
    cudaFuncSetAttribute(pavB_kernel,
                         cudaFuncAttributeMaxDynamicSharedMemorySize, PAVB_SMEM);

    prep_kernel<<<16 + 256, 256>>>(q, M);                        // launch 1
    sim_kernel<<<SIM_BLOCKS, SIM_TPB, SMEM_DYN>>>(               // launch 2
        (const float4*)corpus, sims, M, N);
    pavB_kernel<<<M, PAVB_TPB, PAVB_SMEM>>>(N);                  // launch 3
    int total4 = (M * N) / 4;
    output_kernel<<<(total4 + 255) / 256, 256>>>(                // launch 4
        (const float4*)sims, (float4*)ranks, M, N);
}

// round 15
// speedup vs baseline: 1.5798x; 1.0567x over previous
#include <cuda_runtime.h>
#include <cstdint>

#define DIM   384
#define MAXM  16
#define MAXN  50000
#define NB    4096                 // buckets per row (top 12 bits of sortable key)
#define BSHIFT 20                  // 32 - 12

// fused atomic encoding: contribution = (1<<48) + (v*2^24 + 2^25)
#define VSCALE 16777216.0          // 2^24
#define VBIAS  33554432.0          // 2^25

// ---- sim kernel geometry: 256 threads, 48-doc tiles, K halves -------------
#define TILE_DOCS 48
#define ROWP      388              // padded corpus row stride in floats
#define SIM_TPB   256
#define SIM_BLOCKS 148
#define BFRAG_U2  (2 * 12 * 32)                   // 768 uint2 per table (24 k16-steps)
#define OFF_TA    0
#define OFF_TB    (BFRAG_U2 * 2)                  // floats
#define OFF_TILES (2 * BFRAG_U2 * 2)              // 3072
#define TILE_F    (TILE_DOCS * ROWP)              // 18624
#define OFF_PART  (OFF_TILES + 2 * TILE_F)        // 40320
#define PART_F    (2 * TILE_DOCS * 17)            // 1632: [half][d][q] stride 17
#define OFF_NP    (OFF_PART + PART_F)             // 41952: [half][48] norm partials
#define SMEM_FLOATS (OFF_NP + 2 * TILE_DOCS)
#define SMEM_DYN  (SMEM_FLOATS * (int)sizeof(float))   // ~168 KB

#define PAVB_TPB 256
#define BPT (NB / PAVB_TPB)              // 16 buckets per thread
#define PAVB_SMEM (NB * (int)(sizeof(double) + 2 * sizeof(int)))   // 64 KB

// ---- static device scratch (no allocations allowed) ----
__device__ float              g_qn[MAXM * DIM];
__device__ unsigned long long g_sum[MAXM * NB];   // fused {count:16 | biased fx sum:48}
__device__ float              g_dualf[MAXM * NB];

__device__ __forceinline__ unsigned sortable(float f) {
    unsigned u = __float_as_uint(f);
    return (u & 0x80000000u) ? ~u : (u | 0x80000000u);   // ascending order
}

// pack two f32 -> f16x2 (lo half = first arg, hi half = second arg)
__device__ __forceinline__ unsigned packhf(float lo, float hi) {
    unsigned r;
    asm("cvt.rn.f16x2.f32 %0, %1, %2;" : "=r"(r) : "f"(hi), "f"(lo));
    return r;
}

__device__ __forceinline__ void mma_f16(float c[4], unsigned a0, unsigned a1,
                                        unsigned a2, unsigned a3,
                                        unsigned b0, unsigned b1) {
    asm volatile(
        "mma.sync.aligned.m16n8k16.row.col.f32.f16.f16.f32 "
        "{%0,%1,%2,%3},{%4,%5,%6,%7},{%8,%9},{%0,%1,%2,%3};"
        : "+f"(c[0]), "+f"(c[1]), "+f"(c[2]), "+f"(c[3])
        : "r"(a0), "r"(a1), "r"(a2), "r"(a3), "r"(b0), "r"(b1));
}

// ---- cp.async helpers ----
__device__ __forceinline__ void cp16(void* smem, const void* gmem) {
    unsigned s = (unsigned)__cvta_generic_to_shared(smem);
    asm volatile("cp.async.cg.shared.global [%0], [%1], 16;\n"
                 :: "r"(s), "l"(gmem) : "memory");
}
__device__ __forceinline__ void cp_commit() {
    asm volatile("cp.async.commit_group;\n" ::: "memory");
}
template <int W>
__device__ __forceinline__ void cp_wait() {
    asm volatile("cp.async.wait_group %0;\n" :: "n"(W) : "memory");
}

// ---------------- launch 1: zero fused sums + query normalization ----------
__global__ void prep_kernel(const float* __restrict__ q, int M) {
    if (blockIdx.x < 16) {
        int row = blockIdx.x;
        if (row >= M) return;
        float ss = 0.f;
        for (int i = threadIdx.x; i < DIM; i += blockDim.x) {
            float v = q[row * DIM + i];
            ss += v * v;
        }
        __shared__ float red[256];
        red[threadIdx.x] = ss;
        __syncthreads();
        for (int s = 128; s > 0; s >>= 1) {
            if (threadIdx.x < s) red[threadIdx.x] += red[threadIdx.x + s];
            __syncthreads();
        }
        float inv = 1.f / fmaxf(sqrtf(red[0]), 1e-12f);
        for (int i = threadIdx.x; i < DIM; i += blockDim.x)
            g_qn[row * DIM + i] = q[row * DIM + i] * inv;
    } else {
        int i = (blockIdx.x - 16) * blockDim.x + threadIdx.x;   // 65536
        g_sum[i] = 0ull;
    }
}

// ---------------- launch 2: sims via f16 mma.sync + fused norms ------------
extern __shared__ float shf[];

__global__ void __launch_bounds__(SIM_TPB, 1)
sim_kernel(const float4* __restrict__ corpus4, float* __restrict__ sims,
           int M, int N) {
    uint2* tA    = (uint2*)(shf + OFF_TA);
    uint2* tB    = (uint2*)(shf + OFF_TB);
    float* part  = shf + OFF_PART;               // [half][d][17]
    float* npart = shf + OFF_NP;                 // [half][48]

    int tid  = threadIdx.x;
    int wid  = tid >> 5, lane = tid & 31;
    int g    = lane >> 2, tl = lane & 3;

    // build B fragment tables in SMEM (each warp: 3 k16-steps)
#pragma unroll
    for (int j = 0; j < 3; j++) {
        int gs = wid * 3 + j;                    // 0..23
        int k0 = gs * 16 + 2 * tl;
#pragma unroll
        for (int grp = 0; grp < 2; grp++) {
            const float* qp = g_qn + (grp * 8 + g) * DIM;
            unsigned b0h = packhf(qp[k0],     qp[k0 + 1]);
            unsigned b1h = packhf(qp[k0 + 8], qp[k0 + 9]);
            uint2 r = make_uint2(b0h, b1h);
            if (grp == 0) tA[gs * 32 + lane] = r;
            else          tB[gs * 32 + lane] = r;
        }
    }

    int ntiles = (N + TILE_DOCS - 1) / TILE_DOCS;

    // prefetch first tile (4608 float4, 18 per thread)
    {
        int docbase = blockIdx.x * TILE_DOCS;
        float4* dst = (float4*)(shf + OFF_TILES);
#pragma unroll
        for (int j = 0; j < 18; j++) {
            int idx = tid + j * SIM_TPB;
            int d = idx / 96, c = idx - d * 96;
            int doc = docbase + d;
            if (doc < N) cp16(dst + d * (ROWP / 4) + c, corpus4 + (size_t)doc * 96 + c);
        }
    }
    cp_commit();

    int it = 0;
    for (int t = blockIdx.x; t < ntiles; t += gridDim.x, it++) {
        float* cur = shf + OFF_TILES + (it & 1) * TILE_F;
        float* nxt = shf + OFF_TILES + ((it + 1) & 1) * TILE_F;
        int tn = t + gridDim.x;
        if (tn < ntiles) {
            int docbase = tn * TILE_DOCS;
            float4* dst = (float4*)nxt;
#pragma unroll
            for (int j = 0; j < 18; j++) {
                int idx = tid + j * SIM_TPB;
                int d = idx / 96, c = idx - d * 96;
                int doc = docbase + d;
                if (doc < N) cp16(dst + d * (ROWP / 4) + c, corpus4 + (size_t)doc * 96 + c);
            }
            cp_commit();
            cp_wait<1>();
        } else {
            cp_wait<0>();
        }
        __syncthreads();

        int docbase = t * TILE_DOCS;

        if (wid < 6) {
            // MMA warp: doc-group dg (16 docs), K-half h (192 floats, 12 k16 steps)
            int dg = wid >> 1, h = wid & 1;
            const float* arow0 = cur + (dg * 16 + g) * ROWP;
            const float* arow8 = arow0 + 8 * ROWP;
            const uint2* fA = tA + (h * 12) * 32 + lane;
            const uint2* fB = tB + (h * 12) * 32 + lane;
            float c0[4] = {0.f, 0.f, 0.f, 0.f};   // queries 0-7
            float c1[4] = {0.f, 0.f, 0.f, 0.f};   // queries 8-15
            float ss0 = 0.f, ss1 = 0.f;          // per-lane norm partials, rows g / g+8
            int kbase = h * 192 + 2 * tl;
#pragma unroll
            for (int s = 0; s < 12; s++) {
                int k = kbase + s * 16;
                float2 va0 = *(const float2*)(arow0 + k);
                float2 va1 = *(const float2*)(arow8 + k);
                float2 vb0 = *(const float2*)(arow0 + k + 8);
                float2 vb1 = *(const float2*)(arow8 + k + 8);
                ss0 += va0.x * va0.x + va0.y * va0.y + vb0.x * vb0.x + vb0.y * vb0.y;
                ss1 += va1.x * va1.x + va1.y * va1.y + vb1.x * vb1.x + vb1.y * vb1.y;
                unsigned ah0 = packhf(va0.x, va0.y);
                unsigned ah1 = packhf(va1.x, va1.y);
                unsigned ah2 = packhf(vb0.x, vb0.y);
                unsigned ah3 = packhf(vb1.x, vb1.y);
                uint2 B0 = fA[s * 32];
                uint2 B1 = fB[s * 32];
                mma_f16(c0, ah0, ah1, ah2, ah3, B0.x, B0.y);
                mma_f16(c1, ah0, ah1, ah2, ah3, B1.x, B1.y);
            }
            // reduce norm partials over the 4-lane tl group
            ss0 += __shfl_xor_sync(0xffffffffu, ss0, 1);
            ss0 += __shfl_xor_sync(0xffffffffu, ss0, 2);
            ss1 += __shfl_xor_sync(0xffffffffu, ss1, 1);
            ss1 += __shfl_xor_sync(0xffffffffu, ss1, 2);
            int d0 = dg * 16 + g;
            if (tl == 0) {
                npart[h * TILE_DOCS + d0]     = ss0;
                npart[h * TILE_DOCS + d0 + 8] = ss1;
            }
            // write partials: part[h][d][q], stride 17
            float* pb = part + h * (TILE_DOCS * 17);
            pb[d0 * 17 + tl * 2]           = c0[0];
            pb[d0 * 17 + tl * 2 + 1]       = c0[1];
            pb[(d0 + 8) * 17 + tl * 2]     = c0[2];
            pb[(d0 + 8) * 17 + tl * 2 + 1] = c0[3];
            pb[d0 * 17 + 8 + tl * 2]           = c1[0];
            pb[d0 * 17 + 8 + tl * 2 + 1]       = c1[1];
            pb[(d0 + 8) * 17 + 8 + tl * 2]     = c1[2];
            pb[(d0 + 8) * 17 + 8 + tl * 2 + 1] = c1[3];
        }
        __syncthreads();

        // epilogue: combine halves + norms, write sims + ONE fused atomic
        for (int i = tid; i < TILE_DOCS * 16; i += SIM_TPB) {
            int qq = i / TILE_DOCS;
            int d  = i - qq * TILE_DOCS;
            int doc = docbase + d;
            if (doc < N && qq < M) {
                float n2 = npart[d] + npart[TILE_DOCS + d];
                float v = (part[d * 17 + qq] + part[TILE_DOCS * 17 + d * 17 + qq])
                          * rsqrtf(fmaxf(n2, 1e-24f));
                sims[(size_t)qq * N + doc] = v;
                unsigned b2 = sortable(v) >> BSHIFT;
                long long fx = __double2ll_rn((double)v * VSCALE + VBIAS);
                atomicAdd(&g_sum[qq * NB + b2],
                          (1ull << 48) + (unsigned long long)fx);
            }
        }
        __syncthreads();   // before buffer reuse
    }
}

// ---------------- launch 3: bucket-level PAV, hierarchical merge ------------
__global__ void pavB_kernel(int N) {
    int row = blockIdx.x;
    int t = threadIdx.x;
    int lane = t & 31, ww = t >> 5;     // 8 warps
    extern __shared__ char sm[];
    double* ysum = (double*)sm;          // NB
    int*    cnt  = (int*)(ysum + NB);    // NB
    int*    bend = cnt + NB;             // NB
    __shared__ int snb[PAVB_TPB];
    __shared__ int wnb[8];
    __shared__ int sscan[PAVB_TPB];
    __shared__ int sP;

    // A: coalesced load + decode of fused sums
    for (int b = t; b < NB; b += PAVB_TPB) {
        unsigned long long s = g_sum[row * NB + b];
        int c = (int)(s >> 48);
        double raw = (double)(s & 0xFFFFFFFFFFFFull);
        cnt[b] = c;
        ysum[b] = -10.0 * ((raw - (double)c * VBIAS) / VSCALE);
    }
    __syncthreads();

    // B: per-chunk counts + block-wide exclusive scan of positions
    int base = t * BPT;
    int lc[BPT];
    int tsum = 0;
#pragma unroll
    for (int e = 0; e < BPT; e++) { lc[e] = cnt[base + e]; tsum += lc[e]; }
    sscan[t] = tsum;
    __syncthreads();
    for (int off = 1; off < PAVB_TPB; off <<= 1) {
        int tv = (t >= off) ? sscan[t - off] : 0;
        __syncthreads();
        sscan[t] += tv;
        __syncthreads();
    }
    int run = sscan[t] - tsum;
#pragma unroll
    for (int e = 0; e < BPT; e++) {
        int c = lc[e];
        if (c) {
            ysum[base + e] -= ((double)c * (double)N - (double)c * (double)run
                               - (double)c * (double)(c - 1) * 0.5);
        }
        run += c;
    }

    // C: per-thread chunk PAV
    double lsum[BPT];
    int    lcn[BPT];
    int    lend[BPT];
    int p = 0;
#pragma unroll
    for (int e = 0; e < BPT; e++) {
        int cc = lc[e];
        if (!cc) continue;
        double cs = ysum[base + e];
        while (p > 0 && lsum[p - 1] * (double)cc < cs * (double)lcn[p - 1]) {
            cs += lsum[p - 1]; cc += lcn[p - 1]; p--;
        }
        lsum[p] = cs; lcn[p] = cc; lend[p] = base + e + 1; p++;
    }
    for (int k = 0; k < p; k++) {
        ysum[base + k] = lsum[k]; cnt[base + k] = lcn[k]; bend[base + k] = lend[k];
    }
    snb[t] = p;
    __syncthreads();

    // D: warp-leader merge of 32 chunk lists -> compacted at ww*512
    if (lane == 0) {
        int out = ww * 512;
        int P = 0;
        double TS = 0.0; int TC = 0, TE = 0;
        for (int c = ww * 32; c < ww * 32 + 32; c++) {
            int nb = snb[c];
            int bb = c * BPT;
            for (int k = 0; k < nb; k++) {
                double cs = ysum[bb + k];
                int cc = cnt[bb + k];
                int en = bend[bb + k];
                while (P > 0 && TS * (double)cc < cs * (double)TC) {
                    cs += TS; cc += TC; P--;
                    if (P > 0) { TS = ysum[out + P - 1]; TC = cnt[out + P - 1]; TE = bend[out + P - 1]; }
                }
                if (P > 0) { ysum[out + P - 1] = TS; cnt[out + P - 1] = TC; bend[out + P - 1] = TE; }
                TS = cs; TC = cc; TE = en; P++;
            }
        }
        if (P > 0) { ysum[out + P - 1] = TS; cnt[out + P - 1] = TC; bend[out + P - 1] = TE; }
        wnb[ww] = P;
    }
    __syncthreads();

    // E: thread 0 merges 8 warp lists -> final compacted at 0
    if (t == 0) {
        int P = 0;
        double TS = 0.0; int TC = 0, TE = 0;
        for (int w2 = 0; w2 < 8; w2++) {
            int nb = wnb[w2];
            int bb = w2 * 512;
            for (int k = 0; k < nb; k++) {
                double cs = ysum[bb + k];
                int cc = cnt[bb + k];
                int en = bend[bb + k];
                while (P > 0 && TS * (double)cc < cs * (double)TC) {
                    cs += TS; cc += TC; P--;
                    if (P > 0) { TS = ysum[P - 1]; TC = cnt[P - 1]; TE = bend[P - 1]; }
                }
                if (P > 0) { ysum[P - 1] = TS; cnt[P - 1] = TC; bend[P - 1] = TE; }
                TS = cs; TC = cc; TE = en; P++;
            }
        }
        if (P > 0) { ysum[P - 1] = TS; cnt[P - 1] = TC; bend[P - 1] = TE; }
        sP = P;
    }
    __syncthreads();

    // F: per-bucket dual (float) via binary search over block end-buckets
    int P = sP;
    for (int b = t; b < NB; b += PAVB_TPB) {
        int lo = 0, hi = P - 1;
        while (lo < hi) {
            int mid = (lo + hi) >> 1;
            if (bend[mid] > b) hi = mid; else lo = mid + 1;
        }
        g_dualf[row * NB + b] = (float)(ysum[lo] / (double)cnt[lo]);
    }
}

// ---------------- launch 4: rank output (pure fp32) -------------------------
__global__ void output_kernel(const float4* __restrict__ sims4,
                              float4* __restrict__ ranks4, int M, int N) {
    int i4 = blockIdx.x * blockDim.x + threadIdx.x;
    int total4 = (M * N) >> 2;
    if (i4 >= total4) return;
    int i = i4 * 4;
    int row = i / N;
    float4 v = sims4[i4];
    const float* dr = g_dualf + row * NB;
    float4 o;
    o.x = fmaf(-10.f, v.x, -dr[sortable(v.x) >> BSHIFT]);
    o.y = fmaf(-10.f, v.y, -dr[sortable(v.y) >> BSHIFT]);
    o.z = fmaf(-10.f, v.z, -dr[sortable(v.z) >> BSHIFT]);
    o.w = fmaf(-10.f, v.w, -dr[sortable(v.w) >> BSHIFT]);
    ranks4[i4] = o;
}

// ---------------- host launch ----------------
extern "C" void kernel_launch(void* const* d_in, const int* in_sizes, int n_in,
                              void* d_out, int out_size) {
    const float* q      = (const float*)d_in[0];
    const float* corpus = (const float*)d_in[1];
    int M = in_sizes[0] / DIM;   // 16
    int N = in_sizes[1] / DIM;   // 50000
    if (M > MAXM) M = MAXM;
    if (N > MAXN) N = MAXN;

    float* sims  = (float*)d_out;
    float* ranks = sims + (size_t)M * N;

    cudaFuncSetAttribute(sim_kernel,
                         cudaFuncAttributeMaxDynamicSharedMemorySize, SMEM_DYN);
    cudaFuncSetAttribute(pavB_kernel,
                         cudaFuncAttributeMaxDynamicSharedMemorySize, PAVB_SMEM);

    prep_kernel<<<16 + 256, 256>>>(q, M);                        // launch 1
    sim_kernel<<<SIM_BLOCKS, SIM_TPB, SMEM_DYN>>>(               // launch 2
        (const float4*)corpus, sims, M, N);
    pavB_kernel<<<M, PAVB_TPB, PAVB_SMEM>>>(N);                  // launch 3
    int total4 = (M * N) / 4;
    output_kernel<<<(total4 + 255) / 256, 256>>>(                // launch 4
        (const float4*)sims, (float4*)ranks, M, N);
}

// round 16
// speedup vs baseline: 1.6089x; 1.0185x over previous
#include <cuda_runtime.h>
#include <cstdint>

#define DIM   384
#define MAXM  16
#define MAXN  50000
#define NB    4096                 // buckets per row (top 12 bits of sortable key)
#define BSHIFT 20                  // 32 - 12

// fused atomic encoding: contribution = (1<<48) + (v*2^24 + 2^25)
#define VSCALE 16777216.0          // 2^24
#define VBIAS  33554432.0          // 2^25

// ---- sim kernel geometry: 256 threads, 64-doc tiles, 8 MMA warps ----------
#define TILE_DOCS 64
#define ROWP      388              // padded corpus row stride in floats
#define SIM_TPB   256
#define SIM_BLOCKS 148
#define BFRAG_U2  (2 * 12 * 32)                   // 768 uint2 per table (24 k16-steps)
#define OFF_TA    0
#define OFF_TB    (BFRAG_U2 * 2)                  // floats
#define OFF_TILES (2 * BFRAG_U2 * 2)              // 3072
#define TILE_F    (TILE_DOCS * ROWP)              // 24832
#define OFF_PART  (OFF_TILES + 2 * TILE_F)        // 52736
#define PART_F    (2 * TILE_DOCS * 17)            // 2176: [half][d][q] stride 17
#define OFF_NP    (OFF_PART + PART_F)             // 54912: [half][64] norm partials
#define SMEM_FLOATS (OFF_NP + 2 * TILE_DOCS)      // 55040
#define SMEM_DYN  (SMEM_FLOATS * (int)sizeof(float))   // ~215 KB

#define PAVB_TPB 256
#define BPT (NB / PAVB_TPB)              // 16 buckets per thread
#define PAVB_SMEM (NB * (int)(sizeof(double) + 2 * sizeof(int)))   // 64 KB

// ---- static device scratch (no allocations allowed) ----
__device__ float              g_qn[MAXM * DIM];
__device__ unsigned long long g_sum[MAXM * NB];   // fused {count:16 | biased fx sum:48}
__device__ float              g_dualf[MAXM * NB];

__device__ __forceinline__ unsigned sortable(float f) {
    unsigned u = __float_as_uint(f);
    return (u & 0x80000000u) ? ~u : (u | 0x80000000u);   // ascending order
}

// pack two f32 -> f16x2 (lo half = first arg, hi half = second arg)
__device__ __forceinline__ unsigned packhf(float lo, float hi) {
    unsigned r;
    asm("cvt.rn.f16x2.f32 %0, %1, %2;" : "=r"(r) : "f"(hi), "f"(lo));
    return r;
}

__device__ __forceinline__ void mma_f16(float c[4], unsigned a0, unsigned a1,
                                        unsigned a2, unsigned a3,
                                        unsigned b0, unsigned b1) {
    asm volatile(
        "mma.sync.aligned.m16n8k16.row.col.f32.f16.f16.f32 "
        "{%0,%1,%2,%3},{%4,%5,%6,%7},{%8,%9},{%0,%1,%2,%3};"
        : "+f"(c[0]), "+f"(c[1]), "+f"(c[2]), "+f"(c[3])
        : "r"(a0), "r"(a1), "r"(a2), "r"(a3), "r"(b0), "r"(b1));
}

// ---- cp.async helpers ----
__device__ __forceinline__ void cp16(void* smem, const void* gmem) {
    unsigned s = (unsigned)__cvta_generic_to_shared(smem);
    asm volatile("cp.async.cg.shared.global [%0], [%1], 16;\n"
                 :: "r"(s), "l"(gmem) : "memory");
}
__device__ __forceinline__ void cp_commit() {
    asm volatile("cp.async.commit_group;\n" ::: "memory");
}
template <int W>
__device__ __forceinline__ void cp_wait() {
    asm volatile("cp.async.wait_group %0;\n" :: "n"(W) : "memory");
}

// ---------------- launch 1: zero fused sums + query normalization ----------
__global__ void prep_kernel(const float* __restrict__ q, int M) {
    if (blockIdx.x < 16) {
        int row = blockIdx.x;
        if (row >= M) return;
        float ss = 0.f;
        for (int i = threadIdx.x; i < DIM; i += blockDim.x) {
            float v = q[row * DIM + i];
            ss += v * v;
        }
        __shared__ float red[256];
        red[threadIdx.x] = ss;
        __syncthreads();
        for (int s = 128; s > 0; s >>= 1) {
            if (threadIdx.x < s) red[threadIdx.x] += red[threadIdx.x + s];
            __syncthreads();
        }
        float inv = 1.f / fmaxf(sqrtf(red[0]), 1e-12f);
        for (int i = threadIdx.x; i < DIM; i += blockDim.x)
            g_qn[row * DIM + i] = q[row * DIM + i] * inv;
    } else {
        int i = (blockIdx.x - 16) * blockDim.x + threadIdx.x;   // 65536
        g_sum[i] = 0ull;
    }
}

// ---------------- launch 2: sims via f16 mma.sync, 8 active MMA warps ------
extern __shared__ float shf[];

__global__ void __launch_bounds__(SIM_TPB, 1)
sim_kernel(const float4* __restrict__ corpus4, float* __restrict__ sims,
           int M, int N) {
    uint2* tA    = (uint2*)(shf + OFF_TA);
    uint2* tB    = (uint2*)(shf + OFF_TB);
    float* part  = shf + OFF_PART;               // [half][d][17]
    float* npart = shf + OFF_NP;                 // [half][64]

    int tid  = threadIdx.x;
    int wid  = tid >> 5, lane = tid & 31;
    int g    = lane >> 2, tl = lane & 3;

    // build B fragment tables in SMEM (each warp: 3 k16-steps)
#pragma unroll
    for (int j = 0; j < 3; j++) {
        int gs = wid * 3 + j;                    // 0..23
        int k0 = gs * 16 + 2 * tl;
#pragma unroll
        for (int grp = 0; grp < 2; grp++) {
            const float* qp = g_qn + (grp * 8 + g) * DIM;
            unsigned b0h = packhf(qp[k0],     qp[k0 + 1]);
            unsigned b1h = packhf(qp[k0 + 8], qp[k0 + 9]);
            uint2 r = make_uint2(b0h, b1h);
            if (grp == 0) tA[gs * 32 + lane] = r;
            else          tB[gs * 32 + lane] = r;
        }
    }

    int ntiles = (N + TILE_DOCS - 1) / TILE_DOCS;

    // prefetch first tile (6144 float4, 24 per thread)
    {
        int docbase = blockIdx.x * TILE_DOCS;
        float4* dst = (float4*)(shf + OFF_TILES);
#pragma unroll
        for (int j = 0; j < 24; j++) {
            int idx = tid + j * SIM_TPB;
            int d = idx / 96, c = idx - d * 96;
            int doc = docbase + d;
            if (doc < N) cp16(dst + d * (ROWP / 4) + c, corpus4 + (size_t)doc * 96 + c);
        }
    }
    cp_commit();

    int it = 0;
    for (int t = blockIdx.x; t < ntiles; t += gridDim.x, it++) {
        float* cur = shf + OFF_TILES + (it & 1) * TILE_F;
        float* nxt = shf + OFF_TILES + ((it + 1) & 1) * TILE_F;
        int tn = t + gridDim.x;
        if (tn < ntiles) {
            int docbase = tn * TILE_DOCS;
            float4* dst = (float4*)nxt;
#pragma unroll
            for (int j = 0; j < 24; j++) {
                int idx = tid + j * SIM_TPB;
                int d = idx / 96, c = idx - d * 96;
                int doc = docbase + d;
                if (doc < N) cp16(dst + d * (ROWP / 4) + c, corpus4 + (size_t)doc * 96 + c);
            }
            cp_commit();
            cp_wait<1>();
        } else {
            cp_wait<0>();
        }
        __syncthreads();

        int docbase = t * TILE_DOCS;

        {
            // MMA warp: doc-group dg (16 docs), K-half h (192 floats, 12 k16 steps)
            int dg = wid >> 1, h = wid & 1;
            const float* arow0 = cur + (dg * 16 + g) * ROWP;
            const float* arow8 = arow0 + 8 * ROWP;
            const uint2* fA = tA + (h * 12) * 32 + lane;
            const uint2* fB = tB + (h * 12) * 32 + lane;
            float c0[4] = {0.f, 0.f, 0.f, 0.f};   // queries 0-7
            float c1[4] = {0.f, 0.f, 0.f, 0.f};   // queries 8-15
            float ss0 = 0.f, ss1 = 0.f;          // per-lane norm partials, rows g / g+8
            int kbase = h * 192 + 2 * tl;
#pragma unroll
            for (int s = 0; s < 12; s++) {
                int k = kbase + s * 16;
                float2 va0 = *(const float2*)(arow0 + k);
                float2 va1 = *(const float2*)(arow8 + k);
                float2 vb0 = *(const float2*)(arow0 + k + 8);
                float2 vb1 = *(const float2*)(arow8 + k + 8);
                ss0 += va0.x * va0.x + va0.y * va0.y + vb0.x * vb0.x + vb0.y * vb0.y;
                ss1 += va1.x * va1.x + va1.y * va1.y + vb1.x * vb1.x + vb1.y * vb1.y;
                unsigned ah0 = packhf(va0.x, va0.y);
                unsigned ah1 = packhf(va1.x, va1.y);
                unsigned ah2 = packhf(vb0.x, vb0.y);
                unsigned ah3 = packhf(vb1.x, vb1.y);
                uint2 B0 = fA[s * 32];
                uint2 B1 = fB[s * 32];
                mma_f16(c0, ah0, ah1, ah2, ah3, B0.x, B0.y);
                mma_f16(c1, ah0, ah1, ah2, ah3, B1.x, B1.y);
            }
            // reduce norm partials over the 4-lane tl group
            ss0 += __shfl_xor_sync(0xffffffffu, ss0, 1);
            ss0 += __shfl_xor_sync(0xffffffffu, ss0, 2);
            ss1 += __shfl_xor_sync(0xffffffffu, ss1, 1);
            ss1 += __shfl_xor_sync(0xffffffffu, ss1, 2);
            int d0 = dg * 16 + g;
            if (tl == 0) {
                npart[h * TILE_DOCS + d0]     = ss0;
                npart[h * TILE_DOCS + d0 + 8] = ss1;
            }
            // write partials: part[h][d][q], stride 17
            float* pb = part + h * (TILE_DOCS * 17);
            pb[d0 * 17 + tl * 2]           = c0[0];
            pb[d0 * 17 + tl * 2 + 1]       = c0[1];
            pb[(d0 + 8) * 17 + tl * 2]     = c0[2];
            pb[(d0 + 8) * 17 + tl * 2 + 1] = c0[3];
            pb[d0 * 17 + 8 + tl * 2]           = c1[0];
            pb[d0 * 17 + 8 + tl * 2 + 1]       = c1[1];
            pb[(d0 + 8) * 17 + 8 + tl * 2]     = c1[2];
            pb[(d0 + 8) * 17 + 8 + tl * 2 + 1] = c1[3];
        }
        __syncthreads();

        // epilogue: combine halves + norms, write sims + ONE fused atomic
        for (int i = tid; i < TILE_DOCS * 16; i += SIM_TPB) {
            int qq = i / TILE_DOCS;
            int d  = i - qq * TILE_DOCS;
            int doc = docbase + d;
            if (doc < N && qq < M) {
                float n2 = npart[d] + npart[TILE_DOCS + d];
                float v = (part[d * 17 + qq] + part[TILE_DOCS * 17 + d * 17 + qq])
                          * rsqrtf(fmaxf(n2, 1e-24f));
                sims[(size_t)qq * N + doc] = v;
                unsigned b2 = sortable(v) >> BSHIFT;
                long long fx = __double2ll_rn((double)v * VSCALE + VBIAS);
                atomicAdd(&g_sum[qq * NB + b2],
                          (1ull << 48) + (unsigned long long)fx);
            }
        }
        __syncthreads();   // before buffer reuse
    }
}

// ---------------- launch 3: bucket-level PAV, hierarchical merge ------------
__global__ void pavB_kernel(int N) {
    int row = blockIdx.x;
    int t = threadIdx.x;
    int lane = t & 31, ww = t >> 5;     // 8 warps
    extern __shared__ char sm[];
    double* ysum = (double*)sm;          // NB
    int*    cnt  = (int*)(ysum + NB);    // NB
    int*    bend = cnt + NB;             // NB
    __shared__ int snb[PAVB_TPB];
    __shared__ int wnb[8];
    __shared__ int sscan[PAVB_TPB];
    __shared__ int sP;

    // A: coalesced load + decode of fused sums
    for (int b = t; b < NB; b += PAVB_TPB) {
        unsigned long long s = g_sum[row * NB + b];
        int c = (int)(s >> 48);
        double raw = (double)(s & 0xFFFFFFFFFFFFull);
        cnt[b] = c;
        ysum[b] = -10.0 * ((raw - (double)c * VBIAS) / VSCALE);
    }
    __syncthreads();

    // B: per-chunk counts + block-wide exclusive scan of positions
    int base = t * BPT;
    int lc[BPT];
    int tsum = 0;
#pragma unroll
    for (int e = 0; e < BPT; e++) { lc[e] = cnt[base + e]; tsum += lc[e]; }
    sscan[t] = tsum;
    __syncthreads();
    for (int off = 1; off < PAVB_TPB; off <<= 1) {
        int tv = (t >= off) ? sscan[t - off] : 0;
        __syncthreads();
        sscan[t] += tv;
        __syncthreads();
    }
    int run = sscan[t] - tsum;
#pragma unroll
    for (int e = 0; e < BPT; e++) {
        int c = lc[e];
        if (c) {
            ysum[base + e] -= ((double)c * (double)N - (double)c * (double)run
                               - (double)c * (double)(c - 1) * 0.5);
        }
        run += c;
    }

    // C: per-thread chunk PAV
    double lsum[BPT];
    int    lcn[BPT];
    int    lend[BPT];
    int p = 0;
#pragma unroll
    for (int e = 0; e < BPT; e++) {
        int cc = lc[e];
        if (!cc) continue;
        double cs = ysum[base + e];
        while (p > 0 && lsum[p - 1] * (double)cc < cs * (double)lcn[p - 1]) {
            cs += lsum[p - 1]; cc += lcn[p - 1]; p--;
        }
        lsum[p] = cs; lcn[p] = cc; lend[p] = base + e + 1; p++;
    }
    for (int k = 0; k < p; k++) {
        ysum[base + k] = lsum[k]; cnt[base + k] = lcn[k]; bend[base + k] = lend[k];
    }
    snb[t] = p;
    __syncthreads();

    // D: warp-leader merge of 32 chunk lists -> compacted at ww*512
    if (lane == 0) {
        int out = ww * 512;
        int P = 0;
        double TS = 0.0; int TC = 0, TE = 0;
        for (int c = ww * 32; c < ww * 32 + 32; c++) {
            int nb = snb[c];
            int bb = c * BPT;
            for (int k = 0; k < nb; k++) {
                double cs = ysum[bb + k];
                int cc = cnt[bb + k];
                int en = bend[bb + k];
                while (P > 0 && TS * (double)cc < cs * (double)TC) {
                    cs += TS; cc += TC; P--;
                    if (P > 0) { TS = ysum[out + P - 1]; TC = cnt[out + P - 1]; TE = bend[out + P - 1]; }
                }
                if (P > 0) { ysum[out + P - 1] = TS; cnt[out + P - 1] = TC; bend[out + P - 1] = TE; }
                TS = cs; TC = cc; TE = en; P++;
            }
        }
        if (P > 0) { ysum[out + P - 1] = TS; cnt[out + P - 1] = TC; bend[out + P - 1] = TE; }
        wnb[ww] = P;
    }
    __syncthreads();

    // E: thread 0 merges 8 warp lists -> final compacted at 0
    if (t == 0) {
        int P = 0;
        double TS = 0.0; int TC = 0, TE = 0;
        for (int w2 = 0; w2 < 8; w2++) {
            int nb = wnb[w2];
            int bb = w2 * 512;
            for (int k = 0; k < nb; k++) {
                double cs = ysum[bb + k];
                int cc = cnt[bb + k];
                int en = bend[bb + k];
                while (P > 0 && TS * (double)cc < cs * (double)TC) {
                    cs += TS; cc += TC; P--;
                    if (P > 0) { TS = ysum[P - 1]; TC = cnt[P - 1]; TE = bend[P - 1]; }
                }
                if (P > 0) { ysum[P - 1] = TS; cnt[P - 1] = TC; bend[P - 1] = TE; }
                TS = cs; TC = cc; TE = en; P++;
            }
        }
        if (P > 0) { ysum[P - 1] = TS; cnt[P - 1] = TC; bend[P - 1] = TE; }
        sP = P;
    }
    __syncthreads();

    // F: per-bucket dual (float) via binary search over block end-buckets
    int P = sP;
    for (int b = t; b < NB; b += PAVB_TPB) {
        int lo = 0, hi = P - 1;
        while (lo < hi) {
            int mid = (lo + hi) >> 1;
            if (bend[mid] > b) hi = mid; else lo = mid + 1;
        }
        g_dualf[row * NB + b] = (float)(ysum[lo] / (double)cnt[lo]);
    }
}

// ---------------- launch 4: rank output (pure fp32) -------------------------
__global__ void output_kernel(const float4* __restrict__ sims4,
                              float4* __restrict__ ranks4, int M, int N) {
    int i4 = blockIdx.x * blockDim.x + threadIdx.x;
    int total4 = (M * N) >> 2;
    if (i4 >= total4) return;
    int i = i4 * 4;
    int row = i / N;
    float4 v = sims4[i4];
    const float* dr = g_dualf + row * NB;
    float4 o;
    o.x = fmaf(-10.f, v.x, -dr[sortable(v.x) >> BSHIFT]);
    o.y = fmaf(-10.f, v.y, -dr[sortable(v.y) >> BSHIFT]);
    o.z = fmaf(-10.f, v.z, -dr[sortable(v.z) >> BSHIFT]);
    o.w = fmaf(-10.f, v.w, -dr[sortable(v.w) >> BSHIFT]);
    ranks4[i4] = o;
}

// ---------------- host launch ----------------
extern "C" void kernel_launch(void* const* d_in, const int* in_sizes, int n_in,
                              void* d_out, int out_size) {
    const float* q      = (const float*)d_in[0];
    const float* corpus = (const float*)d_in[1];
    int M = in_sizes[0] / DIM;   // 16
    int N = in_sizes[1] / DIM;   // 50000
    if (M > MAXM) M = MAXM;
    if (N > MAXN) N = MAXN;

    float* sims  = (float*)d_out;
    float* ranks = sims + (size_t)M * N;

    cudaFuncSetAttribute(sim_kernel,
                         cudaFuncAttributeMaxDynamicSharedMemorySize, SMEM_DYN);
    cudaFuncSetAttribute(pavB_kernel,
                         cudaFuncAttributeMaxDynamicSharedMemorySize, PAVB_SMEM);

    prep_kernel<<<16 + 256, 256>>>(q, M);                        // launch 1
    sim_kernel<<<SIM_BLOCKS, SIM_TPB, SMEM_DYN>>>(               // launch 2
        (const float4*)corpus, sims, M, N);
    pavB_kernel<<<M, PAVB_TPB, PAVB_SMEM>>>(N);                  // launch 3
    int total4 = (M * N) / 4;
    output_kernel<<<(total4 + 255) / 256, 256>>>(                // launch 4
        (const float4*)sims, (float4*)ranks, M, N);
}

// round 17
// speedup vs baseline: 1.6726x; 1.0396x over previous
#include <cuda_runtime.h>
#include <cstdint>

#define DIM   384
#define MAXM  16
#define MAXN  50000
#define NB    4096                 // buckets per row (top 12 bits of sortable key)
#define BSHIFT 20                  // 32 - 12

// fused atomic encoding: contribution = (1<<48) + (v*2^24 + 2^25)
#define VSCALE 16777216.0          // 2^24
#define VBIAS  33554432.0          // 2^25

// ---- sim kernel geometry: 256 threads, 64-doc tiles, 8 MMA warps ----------
#define TILE_DOCS 64
#define ROWP      388              // padded corpus row stride in floats
#define SIM_TPB   256
#define SIM_BLOCKS 148
#define BFRAG_U2  (2 * 12 * 32)                   // 768 uint2 per table (24 k16-steps)
#define OFF_TA    0
#define OFF_TB    (BFRAG_U2 * 2)                  // floats
#define OFF_TILES (2 * BFRAG_U2 * 2)              // 3072
#define TILE_F    (TILE_DOCS * ROWP)              // 24832
#define OFF_PART  (OFF_TILES + 2 * TILE_F)        // 52736
#define PART_F    (2 * TILE_DOCS * 17)            // 2176: [half][d][q] stride 17
#define OFF_NP    (OFF_PART + PART_F)             // 54912: [half][64] norm partials
#define SMEM_FLOATS (OFF_NP + 2 * TILE_DOCS)      // 55040
#define SMEM_DYN  (SMEM_FLOATS * (int)sizeof(float))   // ~215 KB

#define PAVB_TPB 256
#define BPT (NB / PAVB_TPB)              // 16 buckets per thread
#define PAVB_SMEM (NB * (int)(sizeof(double) + 2 * sizeof(int)))   // 64 KB

// ---- static device scratch (no allocations allowed) ----
__device__ float              g_qn[MAXM * DIM];
__device__ unsigned long long g_sum[MAXM * NB];   // fused {count:16 | biased fx sum:48}
__device__ float              g_dualf[MAXM * NB];

__device__ __forceinline__ unsigned sortable(float f) {
    unsigned u = __float_as_uint(f);
    return (u & 0x80000000u) ? ~u : (u | 0x80000000u);   // ascending order
}

// pack two f32 -> f16x2 (lo half = first arg, hi half = second arg)
__device__ __forceinline__ unsigned packhf(float lo, float hi) {
    unsigned r;
    asm("cvt.rn.f16x2.f32 %0, %1, %2;" : "=r"(r) : "f"(hi), "f"(lo));
    return r;
}

__device__ __forceinline__ void mma_f16(float c[4], unsigned a0, unsigned a1,
                                        unsigned a2, unsigned a3,
                                        unsigned b0, unsigned b1) {
    asm volatile(
        "mma.sync.aligned.m16n8k16.row.col.f32.f16.f16.f32 "
        "{%0,%1,%2,%3},{%4,%5,%6,%7},{%8,%9},{%0,%1,%2,%3};"
        : "+f"(c[0]), "+f"(c[1]), "+f"(c[2]), "+f"(c[3])
        : "r"(a0), "r"(a1), "r"(a2), "r"(a3), "r"(b0), "r"(b1));
}

// ---- cp.async helpers ----
__device__ __forceinline__ void cp16(void* smem, const void* gmem) {
    unsigned s = (unsigned)__cvta_generic_to_shared(smem);
    asm volatile("cp.async.cg.shared.global [%0], [%1], 16;\n"
                 :: "r"(s), "l"(gmem) : "memory");
}
__device__ __forceinline__ void cp_commit() {
    asm volatile("cp.async.commit_group;\n" ::: "memory");
}
template <int W>
__device__ __forceinline__ void cp_wait() {
    asm volatile("cp.async.wait_group %0;\n" :: "n"(W) : "memory");
}

// ---------------- launch 1: zero fused sums + query normalization ----------
__global__ void prep_kernel(const float* __restrict__ q, int M) {
    if (blockIdx.x < 16) {
        int row = blockIdx.x;
        if (row >= M) return;
        float ss = 0.f;
        for (int i = threadIdx.x; i < DIM; i += blockDim.x) {
            float v = q[row * DIM + i];
            ss += v * v;
        }
        __shared__ float red[256];
        red[threadIdx.x] = ss;
        __syncthreads();
        for (int s = 128; s > 0; s >>= 1) {
            if (threadIdx.x < s) red[threadIdx.x] += red[threadIdx.x + s];
            __syncthreads();
        }
        float inv = 1.f / fmaxf(sqrtf(red[0]), 1e-12f);
        for (int i = threadIdx.x; i < DIM; i += blockDim.x)
            g_qn[row * DIM + i] = q[row * DIM + i] * inv;
    } else {
        int i = (blockIdx.x - 16) * blockDim.x + threadIdx.x;   // 65536
        g_sum[i] = 0ull;
    }
}

// ---------------- launch 2: sims via f16 mma.sync, 8 active MMA warps ------
extern __shared__ float shf[];

__global__ void __launch_bounds__(SIM_TPB, 1)
sim_kernel(const float4* __restrict__ corpus4, float* __restrict__ sims,
           int M, int N) {
    uint2* tA    = (uint2*)(shf + OFF_TA);
    uint2* tB    = (uint2*)(shf + OFF_TB);
    float* part  = shf + OFF_PART;               // [half][d][17]
    float* npart = shf + OFF_NP;                 // [half][64]

    int tid  = threadIdx.x;
    int wid  = tid >> 5, lane = tid & 31;
    int g    = lane >> 2, tl = lane & 3;

    // build B fragment tables in SMEM (each warp: 3 k16-steps)
#pragma unroll
    for (int j = 0; j < 3; j++) {
        int gs = wid * 3 + j;                    // 0..23
        int k0 = gs * 16 + 2 * tl;
#pragma unroll
        for (int grp = 0; grp < 2; grp++) {
            const float* qp = g_qn + (grp * 8 + g) * DIM;
            unsigned b0h = packhf(qp[k0],     qp[k0 + 1]);
            unsigned b1h = packhf(qp[k0 + 8], qp[k0 + 9]);
            uint2 r = make_uint2(b0h, b1h);
            if (grp == 0) tA[gs * 32 + lane] = r;
            else          tB[gs * 32 + lane] = r;
        }
    }

    int ntiles = (N + TILE_DOCS - 1) / TILE_DOCS;

    // prefetch first tile (6144 float4, 24 per thread)
    {
        int docbase = blockIdx.x * TILE_DOCS;
        float4* dst = (float4*)(shf + OFF_TILES);
#pragma unroll
        for (int j = 0; j < 24; j++) {
            int idx = tid + j * SIM_TPB;
            int d = idx / 96, c = idx - d * 96;
            int doc = docbase + d;
            if (doc < N) cp16(dst + d * (ROWP / 4) + c, corpus4 + (size_t)doc * 96 + c);
        }
    }
    cp_commit();

    int it = 0;
    for (int t = blockIdx.x; t < ntiles; t += gridDim.x, it++) {
        float* cur = shf + OFF_TILES + (it & 1) * TILE_F;
        float* nxt = shf + OFF_TILES + ((it + 1) & 1) * TILE_F;
        int tn = t + gridDim.x;
        if (tn < ntiles) {
            int docbase = tn * TILE_DOCS;
            float4* dst = (float4*)nxt;
#pragma unroll
            for (int j = 0; j < 24; j++) {
                int idx = tid + j * SIM_TPB;
                int d = idx / 96, c = idx - d * 96;
                int doc = docbase + d;
                if (doc < N) cp16(dst + d * (ROWP / 4) + c, corpus4 + (size_t)doc * 96 + c);
            }
            cp_commit();
            cp_wait<1>();
        } else {
            cp_wait<0>();
        }
        __syncthreads();

        int docbase = t * TILE_DOCS;

        {
            // MMA warp: doc-group dg (16 docs), K-half h (192 floats, 12 k16 steps)
            int dg = wid >> 1, h = wid & 1;
            const float* arow0 = cur + (dg * 16 + g) * ROWP;
            const float* arow8 = arow0 + 8 * ROWP;
            const uint2* fA = tA + (h * 12) * 32 + lane;
            const uint2* fB = tB + (h * 12) * 32 + lane;
            float c0[4] = {0.f, 0.f, 0.f, 0.f};   // queries 0-7
            float c1[4] = {0.f, 0.f, 0.f, 0.f};   // queries 8-15
            float ss0 = 0.f, ss1 = 0.f;          // per-lane norm partials, rows g / g+8
            int kbase = h * 192 + 2 * tl;
#pragma unroll
            for (int s = 0; s < 12; s++) {
                int k = kbase + s * 16;
                float2 va0 = *(const float2*)(arow0 + k);
                float2 va1 = *(const float2*)(arow8 + k);
                float2 vb0 = *(const float2*)(arow0 + k + 8);
                float2 vb1 = *(const float2*)(arow8 + k + 8);
                ss0 += va0.x * va0.x + va0.y * va0.y + vb0.x * vb0.x + vb0.y * vb0.y;
                ss1 += va1.x * va1.x + va1.y * va1.y + vb1.x * vb1.x + vb1.y * vb1.y;
                unsigned ah0 = packhf(va0.x, va0.y);
                unsigned ah1 = packhf(va1.x, va1.y);
                unsigned ah2 = packhf(vb0.x, vb0.y);
                unsigned ah3 = packhf(vb1.x, vb1.y);
                uint2 B0 = fA[s * 32];
                uint2 B1 = fB[s * 32];
                mma_f16(c0, ah0, ah1, ah2, ah3, B0.x, B0.y);
                mma_f16(c1, ah0, ah1, ah2, ah3, B1.x, B1.y);
            }
            // reduce norm partials over the 4-lane tl group
            ss0 += __shfl_xor_sync(0xffffffffu, ss0, 1);
            ss0 += __shfl_xor_sync(0xffffffffu, ss0, 2);
            ss1 += __shfl_xor_sync(0xffffffffu, ss1, 1);
            ss1 += __shfl_xor_sync(0xffffffffu, ss1, 2);
            int d0 = dg * 16 + g;
            if (tl == 0) {
                npart[h * TILE_DOCS + d0]     = ss0;
                npart[h * TILE_DOCS + d0 + 8] = ss1;
            }
            // write partials: part[h][d][q], stride 17
            float* pb = part + h * (TILE_DOCS * 17);
            pb[d0 * 17 + tl * 2]           = c0[0];
            pb[d0 * 17 + tl * 2 + 1]       = c0[1];
            pb[(d0 + 8) * 17 + tl * 2]     = c0[2];
            pb[(d0 + 8) * 17 + tl * 2 + 1] = c0[3];
            pb[d0 * 17 + 8 + tl * 2]           = c1[0];
            pb[d0 * 17 + 8 + tl * 2 + 1]       = c1[1];
            pb[(d0 + 8) * 17 + 8 + tl * 2]     = c1[2];
            pb[(d0 + 8) * 17 + 8 + tl * 2 + 1] = c1[3];
        }
        __syncthreads();

        // per-doc inverse norm (64 rsqrt per tile, reuse npart[0..63])
        if (tid < TILE_DOCS) {
            float n2 = npart[tid] + npart[TILE_DOCS + tid];
            npart[tid] = rsqrtf(fmaxf(n2, 1e-24f));
        }
        __syncthreads();

        // epilogue: d fixed per thread; qq = tid/64 + 4*it2
        {
            int d   = tid & 63;
            int qb  = tid >> 6;                  // 0..3
            int doc = docbase + d;
            if (doc < N) {
                float invn = npart[d];
                const float* p0 = part + d * 17;
                const float* p1 = part + TILE_DOCS * 17 + d * 17;
#pragma unroll
                for (int it2 = 0; it2 < 4; it2++) {
                    int qq = qb + it2 * 4;
                    if (qq < M) {
                        float v = (p0[qq] + p1[qq]) * invn;
                        sims[(size_t)qq * N + doc] = v;
                        unsigned b2 = sortable(v) >> BSHIFT;
                        long long fx = llrintf(fmaf(v, 16777216.f, 33554432.f));
                        atomicAdd(&g_sum[qq * NB + b2],
                                  (1ull << 48) + (unsigned long long)fx);
                    }
                }
            }
        }
        __syncthreads();   // before buffer reuse
    }
}

// ---------------- launch 3: bucket-level PAV, hierarchical merge ------------
__global__ void pavB_kernel(int N) {
    int row = blockIdx.x;
    int t = threadIdx.x;
    int lane = t & 31, ww = t >> 5;     // 8 warps
    extern __shared__ char sm[];
    double* ysum = (double*)sm;          // NB
    int*    cnt  = (int*)(ysum + NB);    // NB
    int*    bend = cnt + NB;             // NB
    __shared__ int snb[PAVB_TPB];
    __shared__ int wnb[8];
    __shared__ int sscan[PAVB_TPB];
    __shared__ int sP;

    // A: coalesced load + decode of fused sums
    for (int b = t; b < NB; b += PAVB_TPB) {
        unsigned long long s = g_sum[row * NB + b];
        int c = (int)(s >> 48);
        double raw = (double)(s & 0xFFFFFFFFFFFFull);
        cnt[b] = c;
        ysum[b] = -10.0 * ((raw - (double)c * VBIAS) / VSCALE);
    }
    __syncthreads();

    // B: per-chunk counts + block-wide exclusive scan of positions
    int base = t * BPT;
    int lc[BPT];
    int tsum = 0;
#pragma unroll
    for (int e = 0; e < BPT; e++) { lc[e] = cnt[base + e]; tsum += lc[e]; }
    sscan[t] = tsum;
    __syncthreads();
    for (int off = 1; off < PAVB_TPB; off <<= 1) {
        int tv = (t >= off) ? sscan[t - off] : 0;
        __syncthreads();
        sscan[t] += tv;
        __syncthreads();
    }
    int run = sscan[t] - tsum;
#pragma unroll
    for (int e = 0; e < BPT; e++) {
        int c = lc[e];
        if (c) {
            ysum[base + e] -= ((double)c * (double)N - (double)c * (double)run
                               - (double)c * (double)(c - 1) * 0.5);
        }
        run += c;
    }

    // C: per-thread chunk PAV
    double lsum[BPT];
    int    lcn[BPT];
    int    lend[BPT];
    int p = 0;
#pragma unroll
    for (int e = 0; e < BPT; e++) {
        int cc = lc[e];
        if (!cc) continue;
        double cs = ysum[base + e];
        while (p > 0 && lsum[p - 1] * (double)cc < cs * (double)lcn[p - 1]) {
            cs += lsum[p - 1]; cc += lcn[p - 1]; p--;
        }
        lsum[p] = cs; lcn[p] = cc; lend[p] = base + e + 1; p++;
    }
    for (int k = 0; k < p; k++) {
        ysum[base + k] = lsum[k]; cnt[base + k] = lcn[k]; bend[base + k] = lend[k];
    }
    snb[t] = p;
    __syncthreads();

    // D: warp-leader merge of 32 chunk lists -> compacted at ww*512
    if (lane == 0) {
        int out = ww * 512;
        int P = 0;
        double TS = 0.0; int TC = 0, TE = 0;
        for (int c = ww * 32; c < ww * 32 + 32; c++) {
            int nb = snb[c];
            int bb = c * BPT;
            for (int k = 0; k < nb; k++) {
                double cs = ysum[bb + k];
                int cc = cnt[bb + k];
                int en = bend[bb + k];
                while (P > 0 && TS * (double)cc < cs * (double)TC) {
                    cs += TS; cc += TC; P--;
                    if (P > 0) { TS = ysum[out + P - 1]; TC = cnt[out + P - 1]; TE = bend[out + P - 1]; }
                }
                if (P > 0) { ysum[out + P - 1] = TS; cnt[out + P - 1] = TC; bend[out + P - 1] = TE; }
                TS = cs; TC = cc; TE = en; P++;
            }
        }
        if (P > 0) { ysum[out + P - 1] = TS; cnt[out + P - 1] = TC; bend[out + P - 1] = TE; }
        wnb[ww] = P;
    }
    __syncthreads();

    // E: thread 0 merges 8 warp lists -> final compacted at 0
    if (t == 0) {
        int P = 0;
        double TS = 0.0; int TC = 0, TE = 0;
        for (int w2 = 0; w2 < 8; w2++) {
            int nb = wnb[w2];
            int bb = w2 * 512;
            for (int k = 0; k < nb; k++) {
                double cs = ysum[bb + k];
                int cc = cnt[bb + k];
                int en = bend[bb + k];
                while (P > 0 && TS * (double)cc < cs * (double)TC) {
                    cs += TS; cc += TC; P--;
                    if (P > 0) { TS = ysum[P - 1]; TC = cnt[P - 1]; TE = bend[P - 1]; }
                }
                if (P > 0) { ysum[P - 1] = TS; cnt[P - 1] = TC; bend[P - 1] = TE; }
                TS = cs; TC = cc; TE = en; P++;
            }
        }
        if (P > 0) { ysum[P - 1] = TS; cnt[P - 1] = TC; bend[P - 1] = TE; }
        sP = P;
    }
    __syncthreads();

    // F: per-bucket dual (float) via binary search over block end-buckets
    int P = sP;
    for (int b = t; b < NB; b += PAVB_TPB) {
        int lo = 0, hi = P - 1;
        while (lo < hi) {
            int mid = (lo + hi) >> 1;
            if (bend[mid] > b) hi = mid; else lo = mid + 1;
        }
        g_dualf[row * NB + b] = (float)(ysum[lo] / (double)cnt[lo]);
    }
}

// ---------------- launch 4: rank output (pure fp32) -------------------------
__global__ void output_kernel(const float4* __restrict__ sims4,
                              float4* __restrict__ ranks4, int M, int N) {
    int i4 = blockIdx.x * blockDim.x + threadIdx.x;
    int total4 = (M * N) >> 2;
    if (i4 >= total4) return;
    int i = i4 * 4;
    int row = i / N;
    float4 v = sims4[i4];
    const float* dr = g_dualf + row * NB;
    float4 o;
    o.x = fmaf(-10.f, v.x, -dr[sortable(v.x) >> BSHIFT]);
    o.y = fmaf(-10.f, v.y, -dr[sortable(v.y) >> BSHIFT]);
    o.z = fmaf(-10.f, v.z, -dr[sortable(v.z) >> BSHIFT]);
    o.w = fmaf(-10.f, v.w, -dr[sortable(v.w) >> BSHIFT]);
    ranks4[i4] = o;
}

// ---------------- host launch ----------------
extern "C" void kernel_launch(void* const* d_in, const int* in_sizes, int n_in,
                              void* d_out, int out_size) {
    const float* q      = (const float*)d_in[0];
    const float* corpus = (const float*)d_in[1];
    int M = in_sizes[0] / DIM;   // 16
    int N = in_sizes[1] / DIM;   // 50000
    if (M > MAXM) M = MAXM;
    if (N > MAXN) N = MAXN;

    float* sims  = (float*)d_out;
    float* ranks = sims + (size_t)M * N;

    cudaFuncSetAttribute(sim_kernel,
                         cudaFuncAttributeMaxDynamicSharedMemorySize, SMEM_DYN);
    cudaFuncSetAttribute(pavB_kernel,
                         cudaFuncAttributeMaxDynamicSharedMemorySize, PAVB_SMEM);

    prep_kernel<<<16 + 256, 256>>>(q, M);                        // launch 1
    sim_kernel<<<SIM_BLOCKS, SIM_TPB, SMEM_DYN>>>(               // launch 2
        (const float4*)corpus, sims, M, N);
    pavB_kernel<<<M, PAVB_TPB, PAVB_SMEM>>>(N);                  // launch 3
    int total4 = (M * N) / 4;
    output_kernel<<<(total4 + 255) / 256, 256>>>(                // launch 4
        (const float4*)sims, (float4*)ranks, M, N);
}